// round 7
// baseline (speedup 1.0000x reference)
#include <cuda_runtime.h>
#include <cuda_bf16.h>
#include <math.h>
#include <stdint.h>

#define BB  8
#define MM  36
#define DD  512
#define HWW 196
#define TT  64
#define NN  7056
#define NNP 7168          // padded N (multiple of 256)
#define PP  64
#define G2  5.0f
#define GSPLIT 4
#define KRANGE (NNP / GSPLIT)   // 1792

// ---------------- scratch (device globals; no allocation) ----------------
__device__ __nv_bfloat16  d_Vh[BB * NNP * DD];        // V hi, [b][n][d]
__device__ __nv_bfloat16  d_Vl[BB * NNP * DD];        // V lo
__device__ __nv_bfloat16  d_VhT[BB * DD * NNP];       // V hi transposed, [b][d][n]
__device__ __nv_bfloat16  d_VlT[BB * DD * NNP];
__device__ __nv_bfloat16  d_Eh[BB * TT * DD];
__device__ __nv_bfloat16  d_El[BB * TT * DD];
__device__ __nv_bfloat16  d_W4h[(size_t)PP * TT * NNP];
__device__ __nv_bfloat16  d_W4l[(size_t)PP * TT * NNP];
__device__ float d_Gs[GSPLIT][PP * TT * DD];
__device__ float d_normsq[BB * NN];
__device__ float d_u[BB * MM * DD];
__device__ float d_Zt[PP * TT];
__device__ float d_sExp[PP * TT * MM];
__device__ float d_S[PP];
__device__ float d_betas[BB * TT * MM];

// ---------------- warp MMA + cp.async helpers ----------------
__device__ __forceinline__ uint32_t smem_u32(const void* p) {
    uint32_t a;
    asm("{ .reg .u64 t; cvta.to.shared.u64 t, %1; cvt.u32.u64 %0, t; }"
        : "=r"(a) : "l"(p));
    return a;
}
__device__ __forceinline__ void ldmx4(unsigned* r, uint32_t addr) {
    asm volatile("ldmatrix.sync.aligned.m8n8.x4.shared.b16 {%0,%1,%2,%3}, [%4];"
        : "=r"(r[0]), "=r"(r[1]), "=r"(r[2]), "=r"(r[3]) : "r"(addr));
}
__device__ __forceinline__ void mma_bf16(float* c, const unsigned* a, const unsigned* b) {
    asm volatile("mma.sync.aligned.m16n8k16.row.col.f32.bf16.bf16.f32 "
        "{%0,%1,%2,%3}, {%4,%5,%6,%7}, {%8,%9}, {%0,%1,%2,%3};"
        : "+f"(c[0]), "+f"(c[1]), "+f"(c[2]), "+f"(c[3])
        : "r"(a[0]), "r"(a[1]), "r"(a[2]), "r"(a[3]), "r"(b[0]), "r"(b[1]));
}
__device__ __forceinline__ void cpa16(uint32_t dst, const void* src) {
    asm volatile("cp.async.ca.shared.global [%0], [%1], 16;"
        :: "r"(dst), "l"(src) : "memory");
}
#define CP_COMMIT() asm volatile("cp.async.commit_group;" ::: "memory")
#define CP_WAIT1()  asm volatile("cp.async.wait_group 1;" ::: "memory")
__device__ __forceinline__ void bsplit(float v, __nv_bfloat16& h, __nv_bfloat16& l) {
    h = __float2bfloat16(v);
    l = __float2bfloat16(v - __bfloat162float(h));
}

// stage layout (bf16 elems): Ah[64*40], Al[64*40], Bh[256*40], Bl[256*40]
#define OFF_AL (64 * 40)
#define OFF_BH (128 * 40)
#define OFF_BL (128 * 40 + 256 * 40)
#define STAGE_ELEMS (128 * 40 + 512 * 40)   // 25600 elems = 51200 B
#define SMEM_DYN (2 * STAGE_ELEMS * 2)      // 102400 B -> 2 CTAs/SM

// ---------------- kernel 0: zero accumulators + pad regions ----------------
__global__ void k_init() {
    const int PAD = NNP - NN;   // 112
    int idx0 = blockIdx.x * blockDim.x + threadIdx.x;
    int stride = gridDim.x * blockDim.x;
    const __nv_bfloat16 z = __float2bfloat16(0.f);
    for (int idx = idx0; idx < BB * NN; idx += stride) d_normsq[idx] = 0.f;
    for (int idx = idx0; idx < PP * TT; idx += stride) d_Zt[idx] = 0.f;
    for (int idx = idx0; idx < PP * TT * MM; idx += stride) d_sExp[idx] = 0.f;
    for (int idx = idx0; idx < BB * PAD * DD; idx += stride) {
        int b = idx / (PAD * DD), r = idx % (PAD * DD);
        int n = NN + r / DD, d = r % DD;
        size_t o = ((size_t)b * NNP + n) * DD + d;
        d_Vh[o] = z; d_Vl[o] = z;
        int d2 = r / PAD, n2 = NN + r % PAD;
        size_t o2 = ((size_t)b * DD + d2) * NNP + n2;
        d_VhT[o2] = z; d_VlT[o2] = z;
    }
}

// ---------------- kernel: split text into bf16 hi/lo ----------------
__global__ void k_prep(const float* __restrict__ text) {
    int idx = blockIdx.x * 256 + threadIdx.x;
    if (idx < BB * TT * DD) {
        __nv_bfloat16 h, l;
        bsplit(text[idx], h, l);
        d_Eh[idx] = h; d_El[idx] = l;
    }
}

// ---------------- kernel 1: transpose image -> bf16 splits ----------------
__global__ void __launch_bounds__(256) k_transpose(const float* __restrict__ image) {
    __shared__ float tile[32 * 197];
    const int b = blockIdx.z, m = blockIdx.y, d0 = blockIdx.x * 32;
    const float* src = image + ((size_t)(b * MM + m) * DD + d0) * HWW;
    for (int idx = threadIdx.x; idx < 32 * HWW; idx += 256) {
        int dd = idx / HWW, hw = idx % HWW;
        tile[dd * 197 + hw] = src[idx];
    }
    __syncthreads();
    for (int idx = threadIdx.x; idx < HWW * 32; idx += 256) {
        int nl = idx >> 5, dd = idx & 31;
        int w = nl / 14, h = nl % 14;
        float v = tile[dd * 197 + h * 14 + w];
        __nv_bfloat16 hi, lo; bsplit(v, hi, lo);
        size_t o = ((size_t)b * NNP + m * HWW + nl) * DD + d0 + dd;
        d_Vh[o] = hi; d_Vl[o] = lo;
    }
    for (int idx = threadIdx.x; idx < 32 * HWW; idx += 256) {
        int dd = idx / HWW, nl = idx % HWW;
        int w = nl / 14, h = nl % 14;
        float v = tile[dd * 197 + h * 14 + w];
        __nv_bfloat16 hi, lo; bsplit(v, hi, lo);
        size_t o = ((size_t)b * DD + d0 + dd) * NNP + m * HWW + nl;
        d_VhT[o] = hi; d_VlT[o] = lo;
    }
    if (threadIdx.x < HWW) {
        int nl = threadIdx.x;
        int w = nl / 14, h = nl % 14;
        float s = 0.f;
        #pragma unroll
        for (int dd = 0; dd < 32; dd++) {
            float v = tile[dd * 197 + h * 14 + w];
            s = fmaf(v, v, s);
        }
        atomicAdd(&d_normsq[b * NN + m * HWW + nl], s);
    }
}

// ---------------- kernel 2: u[b,m,d] = sum_hw (Vh+Vl) / ||V_row|| ----------------
__global__ void __launch_bounds__(256) k_u() {
    const int m = blockIdx.x, b = blockIdx.y;
    __shared__ float inv[HWW];
    if (threadIdx.x < HWW)
        inv[threadIdx.x] = rsqrtf(d_normsq[b * NN + m * HWW + threadIdx.x]);
    __syncthreads();
    const __nv_bfloat16* vh = d_Vh + ((size_t)b * NNP + m * HWW) * DD;
    const __nv_bfloat16* vl = d_Vl + ((size_t)b * NNP + m * HWW) * DD;
    for (int d = threadIdx.x; d < DD; d += 256) {
        float acc = 0.f;
        for (int hw = 0; hw < HWW; hw++) {
            float v = __bfloat162float(vh[(size_t)hw * DD + d])
                    + __bfloat162float(vl[(size_t)hw * DD + d]);
            acc = fmaf(v, inv[hw], acc);
        }
        d_u[(size_t)(b * MM + m) * DD + d] = acc;
    }
}

// ---------------- shared MMA mainloop body (64 x 256 tile, 8 warps) ----------------
struct Frag { float C[2][8][4]; };

__device__ __forceinline__ void mma_chunk(__nv_bfloat16* stage, int wm, int wn,
                                          int arow, int akoff, int brow, int bkoff,
                                          Frag& f) {
    __nv_bfloat16* sAh = stage;
    __nv_bfloat16* sAl = stage + OFF_AL;
    __nv_bfloat16* sBh = stage + OFF_BH;
    __nv_bfloat16* sBl = stage + OFF_BL;
    #pragma unroll
    for (int ks = 0; ks < 32; ks += 16) {
        unsigned ah[2][4], al[2][4], bf[8][2];
        #pragma unroll
        for (int mi = 0; mi < 2; mi++) {
            int rb = (wm + mi * 16 + arow) * 40 + ks + akoff;
            ldmx4(ah[mi], smem_u32(sAh + rb));
            ldmx4(al[mi], smem_u32(sAl + rb));
        }
        #pragma unroll
        for (int bi = 0; bi < 4; bi++) {
            unsigned r[4];
            ldmx4(r, smem_u32(sBh + (wn + bi * 16 + brow) * 40 + ks + bkoff));
            bf[2 * bi][0] = r[0]; bf[2 * bi][1] = r[1];
            bf[2 * bi + 1][0] = r[2]; bf[2 * bi + 1][1] = r[3];
        }
        #pragma unroll
        for (int mi = 0; mi < 2; mi++)
            #pragma unroll
            for (int nj = 0; nj < 8; nj++) mma_bf16(f.C[mi][nj], ah[mi], bf[nj]);
        #pragma unroll
        for (int mi = 0; mi < 2; mi++)
            #pragma unroll
            for (int nj = 0; nj < 8; nj++) mma_bf16(f.C[mi][nj], al[mi], bf[nj]);
        #pragma unroll
        for (int bi = 0; bi < 4; bi++) {
            unsigned r[4];
            ldmx4(r, smem_u32(sBl + (wn + bi * 16 + brow) * 40 + ks + bkoff));
            bf[2 * bi][0] = r[0]; bf[2 * bi][1] = r[1];
            bf[2 * bi + 1][0] = r[2]; bf[2 * bi + 1][1] = r[3];
        }
        #pragma unroll
        for (int mi = 0; mi < 2; mi++)
            #pragma unroll
            for (int nj = 0; nj < 8; nj++) mma_bf16(f.C[mi][nj], ah[mi], bf[nj]);
    }
}

// ---------------- kernel 3: sim via HMMA + cp.async pipeline + softmax ----------------
__global__ void __launch_bounds__(256, 2) k_sim_mma() {
    extern __shared__ __align__(16) char smem[];
    __shared__ int colm[256];
    __shared__ float psum[64][4][4];
    float* Cs = (float*)smem;                       // epilogue [64][258]

    const int tid = threadIdx.x, lane = tid & 31, wid = tid >> 5;
    const int p = blockIdx.y, i = p >> 3, j = p & 7;
    const int n0 = blockIdx.x * 256;
    const int wm = (wid >> 2) * 32, wn = (wid & 3) * 64;

    Frag f;
    #pragma unroll
    for (int mi = 0; mi < 2; mi++)
        #pragma unroll
        for (int nj = 0; nj < 8; nj++)
            #pragma unroll
            for (int k = 0; k < 4; k++) f.C[mi][nj][k] = 0.f;

    const int lg = lane >> 3;
    const int arow = (lane & 7) + (lg & 1) * 8, akoff = (lg >> 1) * 8;
    const int brow = (lane & 7) + (lg >> 1) * 8, bkoff = (lg & 1) * 8;

    const int lrow = tid >> 2, lq = tid & 3;
    auto load_chunk = [&](int st, int k0) {
        __nv_bfloat16* stage = (__nv_bfloat16*)smem + st * STAGE_ELEMS;
        size_t ao = ((size_t)j * TT + lrow) * DD + k0 + lq * 8;
        cpa16(smem_u32(stage + lrow * 40 + lq * 8), d_Eh + ao);
        cpa16(smem_u32(stage + OFF_AL + lrow * 40 + lq * 8), d_El + ao);
        #pragma unroll
        for (int r = 0; r < 4; r++) {
            int idx = tid + r * 256;
            int row = idx >> 2, q = idx & 3;
            size_t vo = ((size_t)i * NNP + n0 + row) * DD + k0 + q * 8;
            cpa16(smem_u32(stage + OFF_BH + row * 40 + q * 8), d_Vh + vo);
            cpa16(smem_u32(stage + OFF_BL + row * 40 + q * 8), d_Vl + vo);
        }
    };

    load_chunk(0, 0);
    CP_COMMIT();
    const int NCH = DD / 32;   // 16
    for (int ch = 0; ch < NCH; ch++) {
        if (ch + 1 < NCH) load_chunk((ch + 1) & 1, (ch + 1) * 32);
        CP_COMMIT();
        CP_WAIT1();
        __syncthreads();
        mma_chunk((__nv_bfloat16*)smem + (ch & 1) * STAGE_ELEMS,
                  wm, wn, arow, akoff, brow, bkoff, f);
        __syncthreads();
    }

    // ---------------- epilogue ----------------
    #pragma unroll
    for (int mi = 0; mi < 2; mi++)
        #pragma unroll
        for (int nj = 0; nj < 8; nj++) {
            int row = wm + mi * 16 + (lane >> 2);
            int col = wn + nj * 8 + (lane & 3) * 2;
            *(float2*)&Cs[row * 258 + col] = make_float2(f.C[mi][nj][0], f.C[mi][nj][1]);
            *(float2*)&Cs[(row + 8) * 258 + col] = make_float2(f.C[mi][nj][2], f.C[mi][nj][3]);
        }
    colm[tid] = (n0 + tid < NN) ? (n0 + tid) / HWW : -1;
    __syncthreads();

    {   // column softmax over t, write W4 hi/lo
        const int col = tid;
        float mx = -1e30f;
        for (int t = 0; t < TT; t++) mx = fmaxf(mx, Cs[t * 258 + col]);
        float s = 0.f;
        for (int t = 0; t < TT; t++) {
            float e = __expf(Cs[t * 258 + col] - mx);
            s += e;
            Cs[t * 258 + col] = e;
        }
        float inv = 1.f / s;
        __nv_bfloat16* wh = d_W4h + (size_t)p * TT * NNP + n0 + col;
        __nv_bfloat16* wl = d_W4l + (size_t)p * TT * NNP + n0 + col;
        for (int t = 0; t < TT; t++) {
            float ns = Cs[t * 258 + col] * inv;
            float en = __expf(ns);
            Cs[t * 258 + col] = en;
            float e4 = en * en; e4 *= e4;
            __nv_bfloat16 h, l; bsplit(e4, h, l);
            wh[(size_t)t * NNP] = h;
            wl[(size_t)t * NNP] = l;
        }
    }
    __syncthreads();
    {
        const int t = tid >> 2, qc = tid & 3;
        const int m_base = n0 / HWW;
        float z = 0.f, s0 = 0.f, s1 = 0.f, s2 = 0.f;
        for (int c = qc * 64; c < qc * 64 + 64; c++) {
            int bm = colm[c];
            if (bm >= 0) {
                float en = Cs[t * 258 + c];
                float e4 = en * en; e4 *= e4;
                z += e4;
                int sel = bm - m_base;
                if (sel == 0) s0 += en; else if (sel == 1) s1 += en; else s2 += en;
            }
        }
        psum[t][qc][0] = z; psum[t][qc][1] = s0;
        psum[t][qc][2] = s1; psum[t][qc][3] = s2;
    }
    __syncthreads();
    if (tid < TT) {
        float z = 0.f, s0 = 0.f, s1 = 0.f, s2 = 0.f;
        #pragma unroll
        for (int qc = 0; qc < 4; qc++) {
            z += psum[tid][qc][0]; s0 += psum[tid][qc][1];
            s1 += psum[tid][qc][2]; s2 += psum[tid][qc][3];
        }
        const int m_base = n0 / HWW;
        atomicAdd(&d_Zt[p * TT + tid], z);
        atomicAdd(&d_sExp[((size_t)p * TT + tid) * MM + m_base], s0);
        if (m_base + 1 < MM && s1 != 0.f)
            atomicAdd(&d_sExp[((size_t)p * TT + tid) * MM + m_base + 1], s1);
        if (m_base + 2 < MM && s2 != 0.f)
            atomicAdd(&d_sExp[((size_t)p * TT + tid) * MM + m_base + 2], s2);
    }
}

// ---------------- kernel 4: Gs[s][p,t,d] via HMMA + cp.async, N=256 ----------------
__global__ void __launch_bounds__(256, 2) k_gmm_mma() {
    extern __shared__ __align__(16) char smem[];
    const int tid = threadIdx.x, lane = tid & 31, wid = tid >> 5;
    const int p = blockIdx.z, i = p >> 3;
    const int d0 = blockIdx.x * 256;
    const int s = blockIdx.y;
    const int kbase = s * KRANGE;
    const int wm = (wid >> 2) * 32, wn = (wid & 3) * 64;

    Frag f;
    #pragma unroll
    for (int mi = 0; mi < 2; mi++)
        #pragma unroll
        for (int nj = 0; nj < 8; nj++)
            #pragma unroll
            for (int k = 0; k < 4; k++) f.C[mi][nj][k] = 0.f;

    const int lg = lane >> 3;
    const int arow = (lane & 7) + (lg & 1) * 8, akoff = (lg >> 1) * 8;
    const int brow = (lane & 7) + (lg >> 1) * 8, bkoff = (lg & 1) * 8;

    const int lrow = tid >> 2, lq = tid & 3;
    auto load_chunk = [&](int st, int kb) {
        __nv_bfloat16* stage = (__nv_bfloat16*)smem + st * STAGE_ELEMS;
        size_t ao = ((size_t)p * TT + lrow) * NNP + kb + lq * 8;
        cpa16(smem_u32(stage + lrow * 40 + lq * 8), d_W4h + ao);
        cpa16(smem_u32(stage + OFF_AL + lrow * 40 + lq * 8), d_W4l + ao);
        #pragma unroll
        for (int r = 0; r < 4; r++) {
            int idx = tid + r * 256;
            int row = idx >> 2, q = idx & 3;
            size_t bo = ((size_t)i * DD + d0 + row) * NNP + kb + q * 8;
            cpa16(smem_u32(stage + OFF_BH + row * 40 + q * 8), d_VhT + bo);
            cpa16(smem_u32(stage + OFF_BL + row * 40 + q * 8), d_VlT + bo);
        }
    };

    load_chunk(0, kbase);
    CP_COMMIT();
    const int NCH = KRANGE / 32;   // 56
    for (int ch = 0; ch < NCH; ch++) {
        if (ch + 1 < NCH) load_chunk((ch + 1) & 1, kbase + (ch + 1) * 32);
        CP_COMMIT();
        CP_WAIT1();
        __syncthreads();
        mma_chunk((__nv_bfloat16*)smem + (ch & 1) * STAGE_ELEMS,
                  wm, wn, arow, akoff, brow, bkoff, f);
        __syncthreads();
    }

    float* Gp = &d_Gs[s][((size_t)p * TT) * DD + d0];
    #pragma unroll
    for (int mi = 0; mi < 2; mi++)
        #pragma unroll
        for (int nj = 0; nj < 8; nj++) {
            int row = wm + mi * 16 + (lane >> 2);
            int col = wn + nj * 8 + (lane & 3) * 2;
            *(float2*)&Gp[(size_t)row * DD + col] = make_float2(f.C[mi][nj][0], f.C[mi][nj][1]);
            *(float2*)&Gp[(size_t)(row + 8) * DD + col] = make_float2(f.C[mi][nj][2], f.C[mi][nj][3]);
        }
}

// ---------------- kernel 5: per-pair score S[p] ----------------
__global__ void __launch_bounds__(256) k_score(const float* __restrict__ text) {
    const int p = blockIdx.x, i = p >> 3, j = p & 7;
    __shared__ float sbeta[TT * MM];
    __shared__ float sls[MM];
    __shared__ float sdiag[TT];
    __shared__ float snrm[MM], sdot[MM];
    __shared__ float Es[TT * 128];
    const int tid = threadIdx.x, lane = tid & 31, warp = tid >> 5;
    const float* E = text + (size_t)j * TT * DD;

    for (int idx = tid; idx < TT * MM; idx += 256)
        sbeta[idx] = d_sExp[(size_t)p * TT * MM + idx];
    if (tid < MM) { snrm[tid] = 0.f; sdot[tid] = 0.f; }
    __syncthreads();
    if (tid < MM) {
        float s = 0.f;
        for (int t = 0; t < TT; t++) s += sbeta[t * MM + tid];
        sls[tid] = 1.0f / s;
    }
    __syncthreads();
    for (int idx = tid; idx < TT * MM; idx += 256) {
        float v = sbeta[idx] * sls[idx % MM];
        sbeta[idx] = v;
        if (i == j) d_betas[(size_t)i * TT * MM + idx] = v;
    }
    __syncthreads();

    for (int t = warp; t < TT; t += 8) {
        const size_t off = ((size_t)p * TT + t) * DD;
        const float* Er = E + (size_t)t * DD;
        float s = 0.f;
        for (int d = lane; d < DD; d += 32) {
            float g = d_Gs[0][off + d] + d_Gs[1][off + d]
                    + d_Gs[2][off + d] + d_Gs[3][off + d];
            s = fmaf(g, Er[d], s);
        }
        #pragma unroll
        for (int o = 16; o; o >>= 1) s += __shfl_down_sync(0xffffffffu, s, o);
        if (lane == 0) sdiag[t] = s / d_Zt[p * TT + t];
    }

    const float* U = d_u + (size_t)i * MM * DD;
    const int grp = tid >> 7;
    const int dl = tid & 127;
    for (int d0 = 0; d0 < DD; d0 += 128) {
        __syncthreads();
        for (int idx = tid; idx < TT * 128; idx += 256) {
            int t = idx >> 7, dloc = idx & 127;
            Es[idx] = E[(size_t)t * DD + d0 + dloc];
        }
        __syncthreads();
        for (int m = grp; m < MM; m += 2) {
            float v = 0.f;
            #pragma unroll 16
            for (int t = 0; t < TT; t++)
                v = fmaf(sbeta[t * MM + m], Es[t * 128 + dl], v);
            float nr = v * v;
            float dt = v * U[(size_t)m * DD + d0 + dl];
            #pragma unroll
            for (int o = 16; o; o >>= 1) {
                nr += __shfl_down_sync(0xffffffffu, nr, o);
                dt += __shfl_down_sync(0xffffffffu, dt, o);
            }
            if (lane == 0) { atomicAdd(&snrm[m], nr); atomicAdd(&sdot[m], dt); }
        }
    }
    __syncthreads();
    if (tid == 0) {
        float se = 0.f;
        for (int t = 0; t < TT; t++) se += expf(G2 * sdiag[t]);
        float r_qd = (1.0f / G2) * logf(se);
        float sm = 0.f;
        for (int m = 0; m < MM; m++)
            sm += expf(sdot[m] / ((float)HWW * sqrtf(snrm[m])));
        d_S[p] = r_qd + (1.0f / G2) * logf(sm);
    }
}

// ---------------- kernel 6: final scalar ----------------
__global__ void __launch_bounds__(256) k_final(const int* __restrict__ spinds,
                                               float* __restrict__ out) {
    __shared__ float sbm[TT * MM];
    __shared__ float red[8];
    __shared__ float regsum;
    const int tid = threadIdx.x, lane = tid & 31, warp = tid >> 5;
    if (tid == 0) regsum = 0.f;
    for (int b = 0; b < BB; b++) {
        __syncthreads();
        for (int idx = tid; idx < TT * MM; idx += 256)
            sbm[idx] = d_betas[(size_t)b * TT * MM + idx];
        __syncthreads();
        float lsum = 0.f;
        for (int idx = tid; idx < MM * MM; idx += 256) {
            int a = idx / MM, c = idx % MM;
            float v = 0.f;
            for (int t = 0; t < TT; t++)
                v = fmaf(sbm[t * MM + a], sbm[t * MM + c], v);
            lsum = fmaf(v, v, lsum);
        }
        for (int t = tid; t < TT; t += 256) {
            float v = 0.f;
            for (int m = 0; m < MM; m++)
                v = fmaf(sbm[t * MM + m], sbm[t * MM + m], v);
            lsum -= v * v;
        }
        #pragma unroll
        for (int o = 16; o; o >>= 1)
            lsum += __shfl_down_sync(0xffffffffu, lsum, o);
        if (lane == 0) red[warp] = lsum;
        __syncthreads();
        if (tid == 0) {
            float s = 0.f;
            for (int w = 0; w < 8; w++) s += red[w];
            regsum += sqrtf(fmaxf(s, 0.f));
        }
    }
    __syncthreads();
    if (tid == 0) {
        float l1 = 0.f, l2 = 0.f;
        for (int a = 0; a < BB; a++) {
            float num = expf(d_S[a * BB + a]);
            float pdq = 0.f, pqd = 0.f;
            for (int k = 0; k < 5; k++) {
                int sp = spinds[a * 5 + k];
                pdq += expf(d_S[a * BB + sp]);
                pqd += expf(d_S[sp * BB + a]);
            }
            l1 += num / pdq;
            l2 += num / pqd;
        }
        out[0] = -(l1 / BB) - (l2 / BB) + regsum / (float)(BB * TT * MM);
    }
}

// ---------------- launcher ----------------
extern "C" void kernel_launch(void* const* d_in, const int* in_sizes, int n_in,
                              void* d_out, int out_size) {
    const float* image  = (const float*)d_in[0];
    const float* text   = (const float*)d_in[1];
    const int*   spinds = (const int*)d_in[3];
    float* out = (float*)d_out;

    cudaFuncSetAttribute(k_sim_mma, cudaFuncAttributeMaxDynamicSharedMemorySize, SMEM_DYN);
    cudaFuncSetAttribute(k_gmm_mma, cudaFuncAttributeMaxDynamicSharedMemorySize, SMEM_DYN);

    k_init<<<1024, 256>>>();
    k_prep<<<(BB * TT * DD) / 256, 256>>>(text);
    {
        dim3 g(16, MM, BB);
        k_transpose<<<g, 256>>>(image);
    }
    {
        dim3 g(NNP / 256, PP);          // 28 x 64  (4th launch -> profiled)
        k_sim_mma<<<g, 256, SMEM_DYN>>>();
    }
    {
        dim3 g(MM, BB);
        k_u<<<g, 256>>>();
    }
    {
        dim3 g(DD / 256, GSPLIT, PP);   // 2 x 4 x 64
        k_gmm_mma<<<g, 256, SMEM_DYN>>>();
    }
    k_score<<<PP, 256>>>(text);
    k_final<<<1, 256>>>(spinds, out);
}

// round 8
// speedup vs baseline: 1.6879x; 1.6879x over previous
#include <cuda_runtime.h>
#include <cuda_bf16.h>
#include <math.h>
#include <stdint.h>

#define BB  8
#define MM  36
#define DD  512
#define HWW 196
#define TT  64
#define NN  7056
#define NNP 7168          // padded N (multiple of 256)
#define PP  64
#define G2  5.0f
#define GSPLIT 4
#define KRANGE (NNP / GSPLIT)   // 1792

// ---------------- scratch (device globals; no allocation) ----------------
__device__ __nv_bfloat16  d_Vh[BB * NNP * DD];        // V hi, [b][n][d]
__device__ __nv_bfloat16  d_VhT[BB * DD * NNP];       // V hi transposed, [b][d][n]
__device__ __nv_bfloat16  d_Eh[BB * TT * DD];
__device__ __nv_bfloat16  d_El[BB * TT * DD];
__device__ __nv_bfloat16  d_W4h[(size_t)PP * TT * NNP];  // delta = exp(4ns)-1, bf16
__device__ float d_Gs[GSPLIT][PP * TT * DD];          // split partial delta-GEMM
__device__ float d_colsum[BB * DD];                   // exact fp32 col sums of V
__device__ float d_normsq[BB * NN];
__device__ float d_u[BB * MM * DD];
__device__ float d_Zt[PP * TT];
__device__ float d_sExp[PP * TT * MM];
__device__ float d_S[PP];
__device__ float d_betas[BB * TT * MM];

// ---------------- warp MMA + cp.async helpers ----------------
__device__ __forceinline__ uint32_t smem_u32(const void* p) {
    uint32_t a;
    asm("{ .reg .u64 t; cvta.to.shared.u64 t, %1; cvt.u32.u64 %0, t; }"
        : "=r"(a) : "l"(p));
    return a;
}
__device__ __forceinline__ void ldmx4(unsigned* r, uint32_t addr) {
    asm volatile("ldmatrix.sync.aligned.m8n8.x4.shared.b16 {%0,%1,%2,%3}, [%4];"
        : "=r"(r[0]), "=r"(r[1]), "=r"(r[2]), "=r"(r[3]) : "r"(addr));
}
__device__ __forceinline__ void mma_bf16(float* c, const unsigned* a, const unsigned* b) {
    asm volatile("mma.sync.aligned.m16n8k16.row.col.f32.bf16.bf16.f32 "
        "{%0,%1,%2,%3}, {%4,%5,%6,%7}, {%8,%9}, {%0,%1,%2,%3};"
        : "+f"(c[0]), "+f"(c[1]), "+f"(c[2]), "+f"(c[3])
        : "r"(a[0]), "r"(a[1]), "r"(a[2]), "r"(a[3]), "r"(b[0]), "r"(b[1]));
}
__device__ __forceinline__ void cpa16(uint32_t dst, const void* src) {
    asm volatile("cp.async.ca.shared.global [%0], [%1], 16;"
        :: "r"(dst), "l"(src) : "memory");
}
#define CP_COMMIT() asm volatile("cp.async.commit_group;" ::: "memory")
#define CP_WAIT1()  asm volatile("cp.async.wait_group 1;" ::: "memory")
__device__ __forceinline__ void bsplit(float v, __nv_bfloat16& h, __nv_bfloat16& l) {
    h = __float2bfloat16(v);
    l = __float2bfloat16(v - __bfloat162float(h));
}

// k_sim stage (bf16 elems): Ah[64*40], Al[64*40], Bh[256*40]
#define SIM_OFF_AL (64 * 40)
#define SIM_OFF_B  (128 * 40)
#define SIM_STAGE  (128 * 40 + 256 * 40)     // 15360 elems = 30720 B
#define SIM_SMEM   66048                     // max(2 stages, epilogue Cs[64][258])
// k_gmm stage: Ah[64*40], Bh[256*40]
#define GMM_OFF_B  (64 * 40)
#define GMM_STAGE  (64 * 40 + 256 * 40)      // 12800 elems = 25600 B
#define GMM_SMEM   (2 * GMM_STAGE * 2)       // 51200 B

// ---------------- kernel 0: zero accumulators + pad regions ----------------
__global__ void k_init() {
    const int PAD = NNP - NN;   // 112
    int idx0 = blockIdx.x * blockDim.x + threadIdx.x;
    int stride = gridDim.x * blockDim.x;
    const __nv_bfloat16 z = __float2bfloat16(0.f);
    for (int idx = idx0; idx < BB * NN; idx += stride) d_normsq[idx] = 0.f;
    for (int idx = idx0; idx < PP * TT; idx += stride) d_Zt[idx] = 0.f;
    for (int idx = idx0; idx < PP * TT * MM; idx += stride) d_sExp[idx] = 0.f;
    for (int idx = idx0; idx < BB * DD; idx += stride) d_colsum[idx] = 0.f;
    for (int idx = idx0; idx < BB * PAD * DD; idx += stride) {
        int b = idx / (PAD * DD), r = idx % (PAD * DD);
        int n = NN + r / DD, d = r % DD;
        d_Vh[((size_t)b * NNP + n) * DD + d] = z;
        int d2 = r / PAD, n2 = NN + r % PAD;
        d_VhT[((size_t)b * DD + d2) * NNP + n2] = z;
    }
}

// ---------------- kernel: split text into bf16 hi/lo ----------------
__global__ void k_prep(const float* __restrict__ text) {
    int idx = blockIdx.x * 256 + threadIdx.x;
    if (idx < BB * TT * DD) {
        __nv_bfloat16 h, l;
        bsplit(text[idx], h, l);
        d_Eh[idx] = h; d_El[idx] = l;
    }
}

// ---------------- kernel 1: transpose image -> Vh/VhT + norms + colsum ----------------
__global__ void __launch_bounds__(256) k_transpose(const float* __restrict__ image) {
    __shared__ float tile[32 * 197];
    const int b = blockIdx.z, m = blockIdx.y, d0 = blockIdx.x * 32;
    const float* src = image + ((size_t)(b * MM + m) * DD + d0) * HWW;
    for (int idx = threadIdx.x; idx < 32 * HWW; idx += 256) {
        int dd = idx / HWW, hw = idx % HWW;
        tile[dd * 197 + hw] = src[idx];
    }
    __syncthreads();
    for (int idx = threadIdx.x; idx < HWW * 32; idx += 256) {
        int nl = idx >> 5, dd = idx & 31;
        int w = nl / 14, h = nl % 14;
        float v = tile[dd * 197 + h * 14 + w];
        d_Vh[((size_t)b * NNP + m * HWW + nl) * DD + d0 + dd] = __float2bfloat16(v);
    }
    for (int idx = threadIdx.x; idx < 32 * HWW; idx += 256) {
        int dd = idx / HWW, nl = idx % HWW;
        int w = nl / 14, h = nl % 14;
        float v = tile[dd * 197 + h * 14 + w];
        d_VhT[((size_t)b * DD + d0 + dd) * NNP + m * HWW + nl] = __float2bfloat16(v);
    }
    if (threadIdx.x < HWW) {
        int nl = threadIdx.x;
        int w = nl / 14, h = nl % 14;
        float s = 0.f;
        #pragma unroll
        for (int dd = 0; dd < 32; dd++) {
            float v = tile[dd * 197 + h * 14 + w];
            s = fmaf(v, v, s);
        }
        atomicAdd(&d_normsq[b * NN + m * HWW + nl], s);
    }
    if (threadIdx.x < 32) {   // exact fp32 column sums (for W4 = 1 + delta trick)
        int dd = threadIdx.x;
        float s = 0.f;
        for (int hw = 0; hw < HWW; hw++) s += tile[dd * 197 + hw];
        atomicAdd(&d_colsum[b * DD + d0 + dd], s);
    }
}

// ---------------- kernel 2: u[b,m,d] = sum_hw Vh / ||V_row|| ----------------
__global__ void __launch_bounds__(256) k_u() {
    const int m = blockIdx.x, b = blockIdx.y;
    __shared__ float inv[HWW];
    if (threadIdx.x < HWW)
        inv[threadIdx.x] = rsqrtf(d_normsq[b * NN + m * HWW + threadIdx.x]);
    __syncthreads();
    const __nv_bfloat16* vh = d_Vh + ((size_t)b * NNP + m * HWW) * DD;
    for (int d = threadIdx.x; d < DD; d += 256) {
        float acc = 0.f;
        for (int hw = 0; hw < HWW; hw++)
            acc = fmaf(__bfloat162float(vh[(size_t)hw * DD + d]), inv[hw], acc);
        d_u[(size_t)(b * MM + m) * DD + d] = acc;
    }
}

// ---------------- MMA mainloop bodies (64 x 256 tile, 8 warps of 32x64) ----------------
struct Frag { float C[2][8][4]; };

// 2-term: (Ah + Al) x Bh
__device__ __forceinline__ void mma_chunk2(__nv_bfloat16* stage, int wm, int wn,
                                           int arow, int akoff, int brow, int bkoff,
                                           Frag& f) {
    __nv_bfloat16* sAh = stage;
    __nv_bfloat16* sAl = stage + SIM_OFF_AL;
    __nv_bfloat16* sB  = stage + SIM_OFF_B;
    #pragma unroll
    for (int ks = 0; ks < 32; ks += 16) {
        unsigned ah[2][4], al[2][4], bf[8][2];
        #pragma unroll
        for (int mi = 0; mi < 2; mi++) {
            int rb = (wm + mi * 16 + arow) * 40 + ks + akoff;
            ldmx4(ah[mi], smem_u32(sAh + rb));
            ldmx4(al[mi], smem_u32(sAl + rb));
        }
        #pragma unroll
        for (int bi = 0; bi < 4; bi++) {
            unsigned r[4];
            ldmx4(r, smem_u32(sB + (wn + bi * 16 + brow) * 40 + ks + bkoff));
            bf[2 * bi][0] = r[0]; bf[2 * bi][1] = r[1];
            bf[2 * bi + 1][0] = r[2]; bf[2 * bi + 1][1] = r[3];
        }
        #pragma unroll
        for (int mi = 0; mi < 2; mi++)
            #pragma unroll
            for (int nj = 0; nj < 8; nj++) mma_bf16(f.C[mi][nj], ah[mi], bf[nj]);
        #pragma unroll
        for (int mi = 0; mi < 2; mi++)
            #pragma unroll
            for (int nj = 0; nj < 8; nj++) mma_bf16(f.C[mi][nj], al[mi], bf[nj]);
    }
}

// 1-term: Ah x Bh
__device__ __forceinline__ void mma_chunk1(__nv_bfloat16* stage, int wm, int wn,
                                           int arow, int akoff, int brow, int bkoff,
                                           Frag& f) {
    __nv_bfloat16* sAh = stage;
    __nv_bfloat16* sB  = stage + GMM_OFF_B;
    #pragma unroll
    for (int ks = 0; ks < 32; ks += 16) {
        unsigned ah[2][4], bf[8][2];
        #pragma unroll
        for (int mi = 0; mi < 2; mi++)
            ldmx4(ah[mi], smem_u32(sAh + (wm + mi * 16 + arow) * 40 + ks + akoff));
        #pragma unroll
        for (int bi = 0; bi < 4; bi++) {
            unsigned r[4];
            ldmx4(r, smem_u32(sB + (wn + bi * 16 + brow) * 40 + ks + bkoff));
            bf[2 * bi][0] = r[0]; bf[2 * bi][1] = r[1];
            bf[2 * bi + 1][0] = r[2]; bf[2 * bi + 1][1] = r[3];
        }
        #pragma unroll
        for (int mi = 0; mi < 2; mi++)
            #pragma unroll
            for (int nj = 0; nj < 8; nj++) mma_bf16(f.C[mi][nj], ah[mi], bf[nj]);
    }
}

// ---------------- kernel 3: sim via 2-term HMMA + cp.async + softmax ----------------
__global__ void __launch_bounds__(256, 2) k_sim_mma() {
    extern __shared__ __align__(16) char smem[];
    __shared__ int colm[256];
    __shared__ float psum[64][4][4];
    float* Cs = (float*)smem;                       // epilogue [64][258]

    const int tid = threadIdx.x, lane = tid & 31, wid = tid >> 5;
    const int p = blockIdx.y, i = p >> 3, j = p & 7;
    const int n0 = blockIdx.x * 256;
    const int wm = (wid >> 2) * 32, wn = (wid & 3) * 64;

    Frag f;
    #pragma unroll
    for (int mi = 0; mi < 2; mi++)
        #pragma unroll
        for (int nj = 0; nj < 8; nj++)
            #pragma unroll
            for (int k = 0; k < 4; k++) f.C[mi][nj][k] = 0.f;

    const int lg = lane >> 3;
    const int arow = (lane & 7) + (lg & 1) * 8, akoff = (lg >> 1) * 8;
    const int brow = (lane & 7) + (lg >> 1) * 8, bkoff = (lg & 1) * 8;

    const int lrow = tid >> 2, lq = tid & 3;
    auto load_chunk = [&](int st, int k0) {
        __nv_bfloat16* stage = (__nv_bfloat16*)smem + st * SIM_STAGE;
        size_t ao = ((size_t)j * TT + lrow) * DD + k0 + lq * 8;
        cpa16(smem_u32(stage + lrow * 40 + lq * 8), d_Eh + ao);
        cpa16(smem_u32(stage + SIM_OFF_AL + lrow * 40 + lq * 8), d_El + ao);
        #pragma unroll
        for (int r = 0; r < 4; r++) {
            int idx = tid + r * 256;
            int row = idx >> 2, q = idx & 3;
            size_t vo = ((size_t)i * NNP + n0 + row) * DD + k0 + q * 8;
            cpa16(smem_u32(stage + SIM_OFF_B + row * 40 + q * 8), d_Vh + vo);
        }
    };

    load_chunk(0, 0);
    CP_COMMIT();
    const int NCH = DD / 32;   // 16
    for (int ch = 0; ch < NCH; ch++) {
        if (ch + 1 < NCH) load_chunk((ch + 1) & 1, (ch + 1) * 32);
        CP_COMMIT();
        CP_WAIT1();
        __syncthreads();
        mma_chunk2((__nv_bfloat16*)smem + (ch & 1) * SIM_STAGE,
                   wm, wn, arow, akoff, brow, bkoff, f);
        __syncthreads();
    }

    // ---------------- epilogue ----------------
    #pragma unroll
    for (int mi = 0; mi < 2; mi++)
        #pragma unroll
        for (int nj = 0; nj < 8; nj++) {
            int row = wm + mi * 16 + (lane >> 2);
            int col = wn + nj * 8 + (lane & 3) * 2;
            *(float2*)&Cs[row * 258 + col] = make_float2(f.C[mi][nj][0], f.C[mi][nj][1]);
            *(float2*)&Cs[(row + 8) * 258 + col] = make_float2(f.C[mi][nj][2], f.C[mi][nj][3]);
        }
    colm[tid] = (n0 + tid < NN) ? (n0 + tid) / HWW : -1;
    __syncthreads();

    {   // column softmax over t, write delta = exp(4 ns) - 1 as bf16
        const int col = tid;
        float mx = -1e30f;
        for (int t = 0; t < TT; t++) mx = fmaxf(mx, Cs[t * 258 + col]);
        float s = 0.f;
        for (int t = 0; t < TT; t++) {
            float e = __expf(Cs[t * 258 + col] - mx);
            s += e;
            Cs[t * 258 + col] = e;
        }
        float inv = 1.f / s;
        __nv_bfloat16* wh = d_W4h + (size_t)p * TT * NNP + n0 + col;
        for (int t = 0; t < TT; t++) {
            float ns = Cs[t * 258 + col] * inv;
            float en = __expf(ns);
            Cs[t * 258 + col] = en;
            float e4 = en * en; e4 *= e4;
            wh[(size_t)t * NNP] = __float2bfloat16(e4 - 1.0f);
        }
    }
    __syncthreads();
    {
        const int t = tid >> 2, qc = tid & 3;
        const int m_base = n0 / HWW;
        float z = 0.f, s0 = 0.f, s1 = 0.f, s2 = 0.f;
        for (int c = qc * 64; c < qc * 64 + 64; c++) {
            int bm = colm[c];
            if (bm >= 0) {
                float en = Cs[t * 258 + c];
                float e4 = en * en; e4 *= e4;
                z += e4;
                int sel = bm - m_base;
                if (sel == 0) s0 += en; else if (sel == 1) s1 += en; else s2 += en;
            }
        }
        psum[t][qc][0] = z; psum[t][qc][1] = s0;
        psum[t][qc][2] = s1; psum[t][qc][3] = s2;
    }
    __syncthreads();
    if (tid < TT) {
        float z = 0.f, s0 = 0.f, s1 = 0.f, s2 = 0.f;
        #pragma unroll
        for (int qc = 0; qc < 4; qc++) {
            z += psum[tid][qc][0]; s0 += psum[tid][qc][1];
            s1 += psum[tid][qc][2]; s2 += psum[tid][qc][3];
        }
        const int m_base = n0 / HWW;
        atomicAdd(&d_Zt[p * TT + tid], z);
        atomicAdd(&d_sExp[((size_t)p * TT + tid) * MM + m_base], s0);
        if (m_base + 1 < MM && s1 != 0.f)
            atomicAdd(&d_sExp[((size_t)p * TT + tid) * MM + m_base + 1], s1);
        if (m_base + 2 < MM && s2 != 0.f)
            atomicAdd(&d_sExp[((size_t)p * TT + tid) * MM + m_base + 2], s2);
    }
}

// ---------------- kernel 4: Gs[s][p,t,d] = delta-GEMM (1-term HMMA) ----------------
__global__ void __launch_bounds__(256, 2) k_gmm_mma() {
    extern __shared__ __align__(16) char smem[];
    const int tid = threadIdx.x, lane = tid & 31, wid = tid >> 5;
    const int p = blockIdx.z, i = p >> 3;
    const int d0 = blockIdx.x * 256;
    const int s = blockIdx.y;
    const int kbase = s * KRANGE;
    const int wm = (wid >> 2) * 32, wn = (wid & 3) * 64;

    Frag f;
    #pragma unroll
    for (int mi = 0; mi < 2; mi++)
        #pragma unroll
        for (int nj = 0; nj < 8; nj++)
            #pragma unroll
            for (int k = 0; k < 4; k++) f.C[mi][nj][k] = 0.f;

    const int lg = lane >> 3;
    const int arow = (lane & 7) + (lg & 1) * 8, akoff = (lg >> 1) * 8;
    const int brow = (lane & 7) + (lg >> 1) * 8, bkoff = (lg & 1) * 8;

    const int lrow = tid >> 2, lq = tid & 3;
    auto load_chunk = [&](int st, int kb) {
        __nv_bfloat16* stage = (__nv_bfloat16*)smem + st * GMM_STAGE;
        size_t ao = ((size_t)p * TT + lrow) * NNP + kb + lq * 8;
        cpa16(smem_u32(stage + lrow * 40 + lq * 8), d_W4h + ao);
        #pragma unroll
        for (int r = 0; r < 4; r++) {
            int idx = tid + r * 256;
            int row = idx >> 2, q = idx & 3;
            size_t bo = ((size_t)i * DD + d0 + row) * NNP + kb + q * 8;
            cpa16(smem_u32(stage + GMM_OFF_B + row * 40 + q * 8), d_VhT + bo);
        }
    };

    load_chunk(0, kbase);
    CP_COMMIT();
    const int NCH = KRANGE / 32;   // 56
    for (int ch = 0; ch < NCH; ch++) {
        if (ch + 1 < NCH) load_chunk((ch + 1) & 1, kbase + (ch + 1) * 32);
        CP_COMMIT();
        CP_WAIT1();
        __syncthreads();
        mma_chunk1((__nv_bfloat16*)smem + (ch & 1) * GMM_STAGE,
                   wm, wn, arow, akoff, brow, bkoff, f);
        __syncthreads();
    }

    float* Gp = &d_Gs[s][((size_t)p * TT) * DD + d0];
    #pragma unroll
    for (int mi = 0; mi < 2; mi++)
        #pragma unroll
        for (int nj = 0; nj < 8; nj++) {
            int row = wm + mi * 16 + (lane >> 2);
            int col = wn + nj * 8 + (lane & 3) * 2;
            *(float2*)&Gp[(size_t)row * DD + col] = make_float2(f.C[mi][nj][0], f.C[mi][nj][1]);
            *(float2*)&Gp[(size_t)(row + 8) * DD + col] = make_float2(f.C[mi][nj][2], f.C[mi][nj][3]);
        }
}

// ---------------- kernel 5: per-pair score S[p] ----------------
__global__ void __launch_bounds__(256) k_score(const float* __restrict__ text) {
    const int p = blockIdx.x, i = p >> 3, j = p & 7;
    __shared__ float sbeta[TT * MM];
    __shared__ float sls[MM];
    __shared__ float sdiag[TT];
    __shared__ float snrm[MM], sdot[MM];
    __shared__ float Es[TT * 128];
    const int tid = threadIdx.x, lane = tid & 31, warp = tid >> 5;
    const float* E = text + (size_t)j * TT * DD;

    for (int idx = tid; idx < TT * MM; idx += 256)
        sbeta[idx] = d_sExp[(size_t)p * TT * MM + idx];
    if (tid < MM) { snrm[tid] = 0.f; sdot[tid] = 0.f; }
    __syncthreads();
    if (tid < MM) {
        float s = 0.f;
        for (int t = 0; t < TT; t++) s += sbeta[t * MM + tid];
        sls[tid] = 1.0f / s;
    }
    __syncthreads();
    for (int idx = tid; idx < TT * MM; idx += 256) {
        float v = sbeta[idx] * sls[idx % MM];
        sbeta[idx] = v;
        if (i == j) d_betas[(size_t)i * TT * MM + idx] = v;
    }
    __syncthreads();

    // diag[t] = ((sum_s Gs[s][t]) + colsum_i) . e[t] / Zt   (W4 = 1 + delta)
    for (int t = warp; t < TT; t += 8) {
        const size_t off = ((size_t)p * TT + t) * DD;
        const float* Er = E + (size_t)t * DD;
        const float* Ci = d_colsum + i * DD;
        float s = 0.f;
        for (int d = lane; d < DD; d += 32) {
            float g = d_Gs[0][off + d] + d_Gs[1][off + d]
                    + d_Gs[2][off + d] + d_Gs[3][off + d] + Ci[d];
            s = fmaf(g, Er[d], s);
        }
        #pragma unroll
        for (int o = 16; o; o >>= 1) s += __shfl_down_sync(0xffffffffu, s, o);
        if (lane == 0) sdiag[t] = s / d_Zt[p * TT + t];
    }

    const float* U = d_u + (size_t)i * MM * DD;
    const int grp = tid >> 7;
    const int dl = tid & 127;
    for (int d0 = 0; d0 < DD; d0 += 128) {
        __syncthreads();
        for (int idx = tid; idx < TT * 128; idx += 256) {
            int t = idx >> 7, dloc = idx & 127;
            Es[idx] = E[(size_t)t * DD + d0 + dloc];
        }
        __syncthreads();
        for (int m = grp; m < MM; m += 2) {
            float v = 0.f;
            #pragma unroll 16
            for (int t = 0; t < TT; t++)
                v = fmaf(sbeta[t * MM + m], Es[t * 128 + dl], v);
            float nr = v * v;
            float dt = v * U[(size_t)m * DD + d0 + dl];
            #pragma unroll
            for (int o = 16; o; o >>= 1) {
                nr += __shfl_down_sync(0xffffffffu, nr, o);
                dt += __shfl_down_sync(0xffffffffu, dt, o);
            }
            if (lane == 0) { atomicAdd(&snrm[m], nr); atomicAdd(&sdot[m], dt); }
        }
    }
    __syncthreads();
    if (tid == 0) {
        float se = 0.f;
        for (int t = 0; t < TT; t++) se += expf(G2 * sdiag[t]);
        float r_qd = (1.0f / G2) * logf(se);
        float sm = 0.f;
        for (int m = 0; m < MM; m++)
            sm += expf(sdot[m] / ((float)HWW * sqrtf(snrm[m])));
        d_S[p] = r_qd + (1.0f / G2) * logf(sm);
    }
}

// ---------------- kernel 6: final scalar ----------------
__global__ void __launch_bounds__(256) k_final(const int* __restrict__ spinds,
                                               float* __restrict__ out) {
    __shared__ float sbm[TT * MM];
    __shared__ float red[8];
    __shared__ float regsum;
    const int tid = threadIdx.x, lane = tid & 31, warp = tid >> 5;
    if (tid == 0) regsum = 0.f;
    for (int b = 0; b < BB; b++) {
        __syncthreads();
        for (int idx = tid; idx < TT * MM; idx += 256)
            sbm[idx] = d_betas[(size_t)b * TT * MM + idx];
        __syncthreads();
        float lsum = 0.f;
        for (int idx = tid; idx < MM * MM; idx += 256) {
            int a = idx / MM, c = idx % MM;
            float v = 0.f;
            for (int t = 0; t < TT; t++)
                v = fmaf(sbm[t * MM + a], sbm[t * MM + c], v);
            lsum = fmaf(v, v, lsum);
        }
        for (int t = tid; t < TT; t += 256) {
            float v = 0.f;
            for (int m = 0; m < MM; m++)
                v = fmaf(sbm[t * MM + m], sbm[t * MM + m], v);
            lsum -= v * v;
        }
        #pragma unroll
        for (int o = 16; o; o >>= 1)
            lsum += __shfl_down_sync(0xffffffffu, lsum, o);
        if (lane == 0) red[warp] = lsum;
        __syncthreads();
        if (tid == 0) {
            float s = 0.f;
            for (int w = 0; w < 8; w++) s += red[w];
            regsum += sqrtf(fmaxf(s, 0.f));
        }
    }
    __syncthreads();
    if (tid == 0) {
        float l1 = 0.f, l2 = 0.f;
        for (int a = 0; a < BB; a++) {
            float num = expf(d_S[a * BB + a]);
            float pdq = 0.f, pqd = 0.f;
            for (int k = 0; k < 5; k++) {
                int sp = spinds[a * 5 + k];
                pdq += expf(d_S[a * BB + sp]);
                pqd += expf(d_S[sp * BB + a]);
            }
            l1 += num / pdq;
            l2 += num / pqd;
        }
        out[0] = -(l1 / BB) - (l2 / BB) + regsum / (float)(BB * TT * MM);
    }
}

// ---------------- launcher ----------------
extern "C" void kernel_launch(void* const* d_in, const int* in_sizes, int n_in,
                              void* d_out, int out_size) {
    const float* image  = (const float*)d_in[0];
    const float* text   = (const float*)d_in[1];
    const int*   spinds = (const int*)d_in[3];
    float* out = (float*)d_out;

    cudaFuncSetAttribute(k_sim_mma, cudaFuncAttributeMaxDynamicSharedMemorySize, SIM_SMEM);
    cudaFuncSetAttribute(k_gmm_mma, cudaFuncAttributeMaxDynamicSharedMemorySize, GMM_SMEM);

    k_init<<<1024, 256>>>();
    k_prep<<<(BB * TT * DD) / 256, 256>>>(text);
    {
        dim3 g(16, MM, BB);
        k_transpose<<<g, 256>>>(image);
    }
    {
        dim3 g(NNP / 256, PP);          // 28 x 64  (4th launch -> profiled)
        k_sim_mma<<<g, 256, SIM_SMEM>>>();
    }
    {
        dim3 g(MM, BB);
        k_u<<<g, 256>>>();
    }
    {
        dim3 g(DD / 256, GSPLIT, PP);   // 2 x 4 x 64
        k_gmm_mma<<<g, 256, GMM_SMEM>>>();
    }
    k_score<<<PP, 256>>>(text);
    k_final<<<1, 256>>>(spinds, out);
}

// round 9
// speedup vs baseline: 1.8713x; 1.1087x over previous
#include <cuda_runtime.h>
#include <cuda_bf16.h>
#include <math.h>
#include <stdint.h>

#define BB  8
#define MM  36
#define DD  512
#define HWW 196
#define TT  64
#define NN  7056
#define NNP 7168          // padded N (multiple of 256)
#define PP  64
#define G2  5.0f
#define GSPLIT 2
#define KRANGE (NNP / GSPLIT)   // 3584

// ---------------- scratch (device globals; no allocation) ----------------
__device__ __nv_bfloat16  d_Vh[BB * NNP * DD];        // V hi, [b][n][d]
__device__ __nv_bfloat16  d_VhT[BB * DD * NNP];       // V hi transposed, [b][d][n]
__device__ __nv_bfloat16  d_Eh[BB * TT * DD];
__device__ __nv_bfloat16  d_W4h[(size_t)PP * TT * NNP];  // delta = exp(4ns)-1, bf16
__device__ float d_Gs[GSPLIT][PP * TT * DD];          // split partial delta-GEMM
__device__ float d_colsum[BB * DD];                   // exact fp32 col sums of V
__device__ float d_normsq[BB * NN];
__device__ float d_u[BB * MM * DD];
__device__ float d_Zt[PP * TT];
__device__ float d_sExp[PP * TT * MM];
__device__ float d_S[PP];
__device__ float d_betas[BB * TT * MM];

// ---------------- warp MMA + cp.async helpers ----------------
__device__ __forceinline__ uint32_t smem_u32(const void* p) {
    uint32_t a;
    asm("{ .reg .u64 t; cvta.to.shared.u64 t, %1; cvt.u32.u64 %0, t; }"
        : "=r"(a) : "l"(p));
    return a;
}
__device__ __forceinline__ void ldmx4(unsigned* r, uint32_t addr) {
    asm volatile("ldmatrix.sync.aligned.m8n8.x4.shared.b16 {%0,%1,%2,%3}, [%4];"
        : "=r"(r[0]), "=r"(r[1]), "=r"(r[2]), "=r"(r[3]) : "r"(addr));
}
__device__ __forceinline__ void mma_bf16(float* c, const unsigned* a, const unsigned* b) {
    asm volatile("mma.sync.aligned.m16n8k16.row.col.f32.bf16.bf16.f32 "
        "{%0,%1,%2,%3}, {%4,%5,%6,%7}, {%8,%9}, {%0,%1,%2,%3};"
        : "+f"(c[0]), "+f"(c[1]), "+f"(c[2]), "+f"(c[3])
        : "r"(a[0]), "r"(a[1]), "r"(a[2]), "r"(a[3]), "r"(b[0]), "r"(b[1]));
}
__device__ __forceinline__ void cpa16(uint32_t dst, const void* src) {
    asm volatile("cp.async.ca.shared.global [%0], [%1], 16;"
        :: "r"(dst), "l"(src) : "memory");
}
#define CP_COMMIT() asm volatile("cp.async.commit_group;" ::: "memory")
#define CP_WAIT1()  asm volatile("cp.async.wait_group 1;" ::: "memory")

// stage layout (bf16 elems): A[64*40], B[256*40]   (both kernels, 1-term)
#define OFF_B      (64 * 40)
#define STAGE_EL   (64 * 40 + 256 * 40)      // 12800 elems = 25600 B
#define MMA_SMEM   66048                     // max(2 stages=51200, Cs[64][258]=66048)

// ---------------- kernel 0: zero accumulators + pad regions ----------------
__global__ void k_init() {
    const int PAD = NNP - NN;   // 112
    int idx0 = blockIdx.x * blockDim.x + threadIdx.x;
    int stride = gridDim.x * blockDim.x;
    const __nv_bfloat16 z = __float2bfloat16(0.f);
    for (int idx = idx0; idx < BB * NN; idx += stride) d_normsq[idx] = 0.f;
    for (int idx = idx0; idx < PP * TT; idx += stride) d_Zt[idx] = 0.f;
    for (int idx = idx0; idx < PP * TT * MM; idx += stride) d_sExp[idx] = 0.f;
    for (int idx = idx0; idx < BB * DD; idx += stride) d_colsum[idx] = 0.f;
    for (int idx = idx0; idx < BB * PAD * DD; idx += stride) {
        int b = idx / (PAD * DD), r = idx % (PAD * DD);
        int n = NN + r / DD, d = r % DD;
        d_Vh[((size_t)b * NNP + n) * DD + d] = z;
        int d2 = r / PAD, n2 = NN + r % PAD;
        d_VhT[((size_t)b * DD + d2) * NNP + n2] = z;
    }
}

// ---------------- kernel: text -> bf16 ----------------
__global__ void k_prep(const float* __restrict__ text) {
    int idx = blockIdx.x * 256 + threadIdx.x;
    if (idx < BB * TT * DD)
        d_Eh[idx] = __float2bfloat16(text[idx]);
}

// ---------------- kernel 1: transpose image -> Vh/VhT + norms + colsum ----------------
__global__ void __launch_bounds__(256) k_transpose(const float* __restrict__ image) {
    __shared__ float tile[32 * 197];
    const int b = blockIdx.z, m = blockIdx.y, d0 = blockIdx.x * 32;
    const float* src = image + ((size_t)(b * MM + m) * DD + d0) * HWW;
    for (int idx = threadIdx.x; idx < 32 * HWW; idx += 256) {
        int dd = idx / HWW, hw = idx % HWW;
        tile[dd * 197 + hw] = src[idx];
    }
    __syncthreads();
    for (int idx = threadIdx.x; idx < HWW * 32; idx += 256) {
        int nl = idx >> 5, dd = idx & 31;
        int w = nl / 14, h = nl % 14;
        float v = tile[dd * 197 + h * 14 + w];
        d_Vh[((size_t)b * NNP + m * HWW + nl) * DD + d0 + dd] = __float2bfloat16(v);
    }
    for (int idx = threadIdx.x; idx < 32 * HWW; idx += 256) {
        int dd = idx / HWW, nl = idx % HWW;
        int w = nl / 14, h = nl % 14;
        float v = tile[dd * 197 + h * 14 + w];
        d_VhT[((size_t)b * DD + d0 + dd) * NNP + m * HWW + nl] = __float2bfloat16(v);
    }
    if (threadIdx.x < HWW) {
        int nl = threadIdx.x;
        int w = nl / 14, h = nl % 14;
        float s = 0.f;
        #pragma unroll
        for (int dd = 0; dd < 32; dd++) {
            float v = tile[dd * 197 + h * 14 + w];
            s = fmaf(v, v, s);
        }
        atomicAdd(&d_normsq[b * NN + m * HWW + nl], s);
    }
    if (threadIdx.x < 32) {   // exact fp32 column sums (for W4 = 1 + delta trick)
        int dd = threadIdx.x;
        float s = 0.f;
        for (int hw = 0; hw < HWW; hw++) s += tile[dd * 197 + hw];
        atomicAdd(&d_colsum[b * DD + d0 + dd], s);
    }
}

// ---------------- kernel 2: u[b,m,d] = sum_hw Vh / ||V_row|| ----------------
__global__ void __launch_bounds__(256) k_u() {
    const int m = blockIdx.x, b = blockIdx.y;
    __shared__ float inv[HWW];
    if (threadIdx.x < HWW)
        inv[threadIdx.x] = rsqrtf(d_normsq[b * NN + m * HWW + threadIdx.x]);
    __syncthreads();
    const __nv_bfloat16* vh = d_Vh + ((size_t)b * NNP + m * HWW) * DD;
    for (int d = threadIdx.x; d < DD; d += 256) {
        float acc = 0.f;
        for (int hw = 0; hw < HWW; hw++)
            acc = fmaf(__bfloat162float(vh[(size_t)hw * DD + d]), inv[hw], acc);
        d_u[(size_t)(b * MM + m) * DD + d] = acc;
    }
}

// ---------------- 1-term MMA mainloop body (64 x 256 tile, 8 warps of 32x64) ----------------
struct Frag { float C[2][8][4]; };

__device__ __forceinline__ void mma_chunk1(__nv_bfloat16* stage, int wm, int wn,
                                           int arow, int akoff, int brow, int bkoff,
                                           Frag& f) {
    __nv_bfloat16* sA = stage;
    __nv_bfloat16* sB = stage + OFF_B;
    #pragma unroll
    for (int ks = 0; ks < 32; ks += 16) {
        unsigned ah[2][4], bf[8][2];
        #pragma unroll
        for (int mi = 0; mi < 2; mi++)
            ldmx4(ah[mi], smem_u32(sA + (wm + mi * 16 + arow) * 40 + ks + akoff));
        #pragma unroll
        for (int bi = 0; bi < 4; bi++) {
            unsigned r[4];
            ldmx4(r, smem_u32(sB + (wn + bi * 16 + brow) * 40 + ks + bkoff));
            bf[2 * bi][0] = r[0]; bf[2 * bi][1] = r[1];
            bf[2 * bi + 1][0] = r[2]; bf[2 * bi + 1][1] = r[3];
        }
        #pragma unroll
        for (int mi = 0; mi < 2; mi++)
            #pragma unroll
            for (int nj = 0; nj < 8; nj++) mma_bf16(f.C[mi][nj], ah[mi], bf[nj]);
    }
}

// ---------------- kernel 3: sim via 1-term HMMA + cp.async + softmax ----------------
__global__ void __launch_bounds__(256, 2) k_sim_mma() {
    extern __shared__ __align__(16) char smem[];
    __shared__ int colm[256];
    __shared__ float psum[64][4][4];
    float* Cs = (float*)smem;                       // epilogue [64][258]

    const int tid = threadIdx.x, lane = tid & 31, wid = tid >> 5;
    const int p = blockIdx.y, i = p >> 3, j = p & 7;
    const int n0 = blockIdx.x * 256;
    const int wm = (wid >> 2) * 32, wn = (wid & 3) * 64;

    Frag f;
    #pragma unroll
    for (int mi = 0; mi < 2; mi++)
        #pragma unroll
        for (int nj = 0; nj < 8; nj++)
            #pragma unroll
            for (int k = 0; k < 4; k++) f.C[mi][nj][k] = 0.f;

    const int lg = lane >> 3;
    const int arow = (lane & 7) + (lg & 1) * 8, akoff = (lg >> 1) * 8;
    const int brow = (lane & 7) + (lg >> 1) * 8, bkoff = (lg & 1) * 8;

    const int lrow = tid >> 2, lq = tid & 3;
    auto load_chunk = [&](int st, int k0) {
        __nv_bfloat16* stage = (__nv_bfloat16*)smem + st * STAGE_EL;
        size_t ao = ((size_t)j * TT + lrow) * DD + k0 + lq * 8;
        cpa16(smem_u32(stage + lrow * 40 + lq * 8), d_Eh + ao);
        #pragma unroll
        for (int r = 0; r < 4; r++) {
            int idx = tid + r * 256;
            int row = idx >> 2, q = idx & 3;
            size_t vo = ((size_t)i * NNP + n0 + row) * DD + k0 + q * 8;
            cpa16(smem_u32(stage + OFF_B + row * 40 + q * 8), d_Vh + vo);
        }
    };

    load_chunk(0, 0);
    CP_COMMIT();
    const int NCH = DD / 32;   // 16
    for (int ch = 0; ch < NCH; ch++) {
        if (ch + 1 < NCH) load_chunk((ch + 1) & 1, (ch + 1) * 32);
        CP_COMMIT();
        CP_WAIT1();
        __syncthreads();
        mma_chunk1((__nv_bfloat16*)smem + (ch & 1) * STAGE_EL,
                   wm, wn, arow, akoff, brow, bkoff, f);
        __syncthreads();
    }

    // ---------------- epilogue ----------------
    #pragma unroll
    for (int mi = 0; mi < 2; mi++)
        #pragma unroll
        for (int nj = 0; nj < 8; nj++) {
            int row = wm + mi * 16 + (lane >> 2);
            int col = wn + nj * 8 + (lane & 3) * 2;
            *(float2*)&Cs[row * 258 + col] = make_float2(f.C[mi][nj][0], f.C[mi][nj][1]);
            *(float2*)&Cs[(row + 8) * 258 + col] = make_float2(f.C[mi][nj][2], f.C[mi][nj][3]);
        }
    colm[tid] = (n0 + tid < NN) ? (n0 + tid) / HWW : -1;
    __syncthreads();

    {   // column softmax over t, write delta = exp(4 ns) - 1 as bf16
        const int col = tid;
        float mx = -1e30f;
        for (int t = 0; t < TT; t++) mx = fmaxf(mx, Cs[t * 258 + col]);
        float s = 0.f;
        for (int t = 0; t < TT; t++) {
            float e = __expf(Cs[t * 258 + col] - mx);
            s += e;
            Cs[t * 258 + col] = e;
        }
        float inv = 1.f / s;
        __nv_bfloat16* wh = d_W4h + (size_t)p * TT * NNP + n0 + col;
        for (int t = 0; t < TT; t++) {
            float ns = Cs[t * 258 + col] * inv;
            float en = __expf(ns);
            Cs[t * 258 + col] = en;
            float e4 = en * en; e4 *= e4;
            wh[(size_t)t * NNP] = __float2bfloat16(e4 - 1.0f);
        }
    }
    __syncthreads();
    {
        const int t = tid >> 2, qc = tid & 3;
        const int m_base = n0 / HWW;
        float z = 0.f, s0 = 0.f, s1 = 0.f, s2 = 0.f;
        for (int c = qc * 64; c < qc * 64 + 64; c++) {
            int bm = colm[c];
            if (bm >= 0) {
                float en = Cs[t * 258 + c];
                float e4 = en * en; e4 *= e4;
                z += e4;
                int sel = bm - m_base;
                if (sel == 0) s0 += en; else if (sel == 1) s1 += en; else s2 += en;
            }
        }
        psum[t][qc][0] = z; psum[t][qc][1] = s0;
        psum[t][qc][2] = s1; psum[t][qc][3] = s2;
    }
    __syncthreads();
    if (tid < TT) {
        float z = 0.f, s0 = 0.f, s1 = 0.f, s2 = 0.f;
        #pragma unroll
        for (int qc = 0; qc < 4; qc++) {
            z += psum[tid][qc][0]; s0 += psum[tid][qc][1];
            s1 += psum[tid][qc][2]; s2 += psum[tid][qc][3];
        }
        const int m_base = n0 / HWW;
        atomicAdd(&d_Zt[p * TT + tid], z);
        atomicAdd(&d_sExp[((size_t)p * TT + tid) * MM + m_base], s0);
        if (m_base + 1 < MM && s1 != 0.f)
            atomicAdd(&d_sExp[((size_t)p * TT + tid) * MM + m_base + 1], s1);
        if (m_base + 2 < MM && s2 != 0.f)
            atomicAdd(&d_sExp[((size_t)p * TT + tid) * MM + m_base + 2], s2);
    }
}

// ---------------- kernel 4: Gs[s][p,t,d] = delta-GEMM (1-term HMMA) ----------------
__global__ void __launch_bounds__(256, 2) k_gmm_mma() {
    extern __shared__ __align__(16) char smem[];
    const int tid = threadIdx.x, lane = tid & 31, wid = tid >> 5;
    const int p = blockIdx.z, i = p >> 3;
    const int d0 = blockIdx.x * 256;
    const int s = blockIdx.y;
    const int kbase = s * KRANGE;
    const int wm = (wid >> 2) * 32, wn = (wid & 3) * 64;

    Frag f;
    #pragma unroll
    for (int mi = 0; mi < 2; mi++)
        #pragma unroll
        for (int nj = 0; nj < 8; nj++)
            #pragma unroll
            for (int k = 0; k < 4; k++) f.C[mi][nj][k] = 0.f;

    const int lg = lane >> 3;
    const int arow = (lane & 7) + (lg & 1) * 8, akoff = (lg >> 1) * 8;
    const int brow = (lane & 7) + (lg >> 1) * 8, bkoff = (lg & 1) * 8;

    const int lrow = tid >> 2, lq = tid & 3;
    auto load_chunk = [&](int st, int kb) {
        __nv_bfloat16* stage = (__nv_bfloat16*)smem + st * STAGE_EL;
        size_t ao = ((size_t)p * TT + lrow) * NNP + kb + lq * 8;
        cpa16(smem_u32(stage + lrow * 40 + lq * 8), d_W4h + ao);
        #pragma unroll
        for (int r = 0; r < 4; r++) {
            int idx = tid + r * 256;
            int row = idx >> 2, q = idx & 3;
            size_t bo = ((size_t)i * DD + d0 + row) * NNP + kb + q * 8;
            cpa16(smem_u32(stage + OFF_B + row * 40 + q * 8), d_VhT + bo);
        }
    };

    load_chunk(0, kbase);
    CP_COMMIT();
    const int NCH = KRANGE / 32;   // 112
    for (int ch = 0; ch < NCH; ch++) {
        if (ch + 1 < NCH) load_chunk((ch + 1) & 1, kbase + (ch + 1) * 32);
        CP_COMMIT();
        CP_WAIT1();
        __syncthreads();
        mma_chunk1((__nv_bfloat16*)smem + (ch & 1) * STAGE_EL,
                   wm, wn, arow, akoff, brow, bkoff, f);
        __syncthreads();
    }

    float* Gp = &d_Gs[s][((size_t)p * TT) * DD + d0];
    #pragma unroll
    for (int mi = 0; mi < 2; mi++)
        #pragma unroll
        for (int nj = 0; nj < 8; nj++) {
            int row = wm + mi * 16 + (lane >> 2);
            int col = wn + nj * 8 + (lane & 3) * 2;
            *(float2*)&Gp[(size_t)row * DD + col] = make_float2(f.C[mi][nj][0], f.C[mi][nj][1]);
            *(float2*)&Gp[(size_t)(row + 8) * DD + col] = make_float2(f.C[mi][nj][2], f.C[mi][nj][3]);
        }
}

// ---------------- kernel 5: per-pair score S[p] ----------------
__global__ void __launch_bounds__(256) k_score(const float* __restrict__ text) {
    const int p = blockIdx.x, i = p >> 3, j = p & 7;
    __shared__ float sbeta[TT * MM];
    __shared__ float sls[MM];
    __shared__ float sdiag[TT];
    __shared__ float snrm[MM], sdot[MM];
    __shared__ float Es[TT * 128];
    const int tid = threadIdx.x, lane = tid & 31, warp = tid >> 5;
    const float* E = text + (size_t)j * TT * DD;

    for (int idx = tid; idx < TT * MM; idx += 256)
        sbeta[idx] = d_sExp[(size_t)p * TT * MM + idx];
    if (tid < MM) { snrm[tid] = 0.f; sdot[tid] = 0.f; }
    __syncthreads();
    if (tid < MM) {
        float s = 0.f;
        for (int t = 0; t < TT; t++) s += sbeta[t * MM + tid];
        sls[tid] = 1.0f / s;
    }
    __syncthreads();
    for (int idx = tid; idx < TT * MM; idx += 256) {
        float v = sbeta[idx] * sls[idx % MM];
        sbeta[idx] = v;
        if (i == j) d_betas[(size_t)i * TT * MM + idx] = v;
    }
    __syncthreads();

    // diag[t] = ((sum_s Gs[s][t]) + colsum_i) . e[t] / Zt   (W4 = 1 + delta)
    for (int t = warp; t < TT; t += 8) {
        const size_t off = ((size_t)p * TT + t) * DD;
        const float* Er = E + (size_t)t * DD;
        const float* Ci = d_colsum + i * DD;
        float s = 0.f;
        for (int d = lane; d < DD; d += 32) {
            float g = d_Gs[0][off + d] + d_Gs[1][off + d] + Ci[d];
            s = fmaf(g, Er[d], s);
        }
        #pragma unroll
        for (int o = 16; o; o >>= 1) s += __shfl_down_sync(0xffffffffu, s, o);
        if (lane == 0) sdiag[t] = s / d_Zt[p * TT + t];
    }

    const float* U = d_u + (size_t)i * MM * DD;
    const int grp = tid >> 7;
    const int dl = tid & 127;
    for (int d0 = 0; d0 < DD; d0 += 128) {
        __syncthreads();
        for (int idx = tid; idx < TT * 128; idx += 256) {
            int t = idx >> 7, dloc = idx & 127;
            Es[idx] = E[(size_t)t * DD + d0 + dloc];
        }
        __syncthreads();
        for (int m = grp; m < MM; m += 2) {
            float v = 0.f;
            #pragma unroll 16
            for (int t = 0; t < TT; t++)
                v = fmaf(sbeta[t * MM + m], Es[t * 128 + dl], v);
            float nr = v * v;
            float dt = v * U[(size_t)m * DD + d0 + dl];
            #pragma unroll
            for (int o = 16; o; o >>= 1) {
                nr += __shfl_down_sync(0xffffffffu, nr, o);
                dt += __shfl_down_sync(0xffffffffu, dt, o);
            }
            if (lane == 0) { atomicAdd(&snrm[m], nr); atomicAdd(&sdot[m], dt); }
        }
    }
    __syncthreads();
    if (tid == 0) {
        float se = 0.f;
        for (int t = 0; t < TT; t++) se += expf(G2 * sdiag[t]);
        float r_qd = (1.0f / G2) * logf(se);
        float sm = 0.f;
        for (int m = 0; m < MM; m++)
            sm += expf(sdot[m] / ((float)HWW * sqrtf(snrm[m])));
        d_S[p] = r_qd + (1.0f / G2) * logf(sm);
    }
}

// ---------------- kernel 6: final scalar ----------------
__global__ void __launch_bounds__(256) k_final(const int* __restrict__ spinds,
                                               float* __restrict__ out) {
    __shared__ float sbm[TT * MM];
    __shared__ float red[8];
    __shared__ float regsum;
    const int tid = threadIdx.x, lane = tid & 31, warp = tid >> 5;
    if (tid == 0) regsum = 0.f;
    for (int b = 0; b < BB; b++) {
        __syncthreads();
        for (int idx = tid; idx < TT * MM; idx += 256)
            sbm[idx] = d_betas[(size_t)b * TT * MM + idx];
        __syncthreads();
        float lsum = 0.f;
        for (int idx = tid; idx < MM * MM; idx += 256) {
            int a = idx / MM, c = idx % MM;
            float v = 0.f;
            for (int t = 0; t < TT; t++)
                v = fmaf(sbm[t * MM + a], sbm[t * MM + c], v);
            lsum = fmaf(v, v, lsum);
        }
        for (int t = tid; t < TT; t += 256) {
            float v = 0.f;
            for (int m = 0; m < MM; m++)
                v = fmaf(sbm[t * MM + m], sbm[t * MM + m], v);
            lsum -= v * v;
        }
        #pragma unroll
        for (int o = 16; o; o >>= 1)
            lsum += __shfl_down_sync(0xffffffffu, lsum, o);
        if (lane == 0) red[warp] = lsum;
        __syncthreads();
        if (tid == 0) {
            float s = 0.f;
            for (int w = 0; w < 8; w++) s += red[w];
            regsum += sqrtf(fmaxf(s, 0.f));
        }
    }
    __syncthreads();
    if (tid == 0) {
        float l1 = 0.f, l2 = 0.f;
        for (int a = 0; a < BB; a++) {
            float num = expf(d_S[a * BB + a]);
            float pdq = 0.f, pqd = 0.f;
            for (int k = 0; k < 5; k++) {
                int sp = spinds[a * 5 + k];
                pdq += expf(d_S[a * BB + sp]);
                pqd += expf(d_S[sp * BB + a]);
            }
            l1 += num / pdq;
            l2 += num / pqd;
        }
        out[0] = -(l1 / BB) - (l2 / BB) + regsum / (float)(BB * TT * MM);
    }
}

// ---------------- launcher ----------------
extern "C" void kernel_launch(void* const* d_in, const int* in_sizes, int n_in,
                              void* d_out, int out_size) {
    const float* image  = (const float*)d_in[0];
    const float* text   = (const float*)d_in[1];
    const int*   spinds = (const int*)d_in[3];
    float* out = (float*)d_out;

    cudaFuncSetAttribute(k_sim_mma, cudaFuncAttributeMaxDynamicSharedMemorySize, MMA_SMEM);
    cudaFuncSetAttribute(k_gmm_mma, cudaFuncAttributeMaxDynamicSharedMemorySize, MMA_SMEM);

    k_init<<<1024, 256>>>();
    k_prep<<<(BB * TT * DD) / 256, 256>>>(text);
    {
        dim3 g(16, MM, BB);
        k_transpose<<<g, 256>>>(image);
    }
    {
        dim3 g(NNP / 256, PP);          // 28 x 64  (4th launch -> profiled)
        k_sim_mma<<<g, 256, MMA_SMEM>>>();
    }
    {
        dim3 g(MM, BB);
        k_u<<<g, 256>>>();
    }
    {
        dim3 g(DD / 256, GSPLIT, PP);   // 2 x 2 x 64
        k_gmm_mma<<<g, 256, MMA_SMEM>>>();
    }
    k_score<<<PP, 256>>>(text);
    k_final<<<1, 256>>>(spinds, out);
}

// round 10
// speedup vs baseline: 1.9051x; 1.0180x over previous
#include <cuda_runtime.h>
#include <cuda_bf16.h>
#include <math.h>
#include <stdint.h>

#define BB  8
#define MM  36
#define DD  512
#define HWW 196
#define TT  64
#define NN  7056
#define NNP 7168          // padded N (multiple of 256)
#define PP  64
#define G2  5.0f
#define GSPLIT 2
#define KRANGE (NNP / GSPLIT)   // 3584

// ---------------- scratch (device globals; no allocation) ----------------
__device__ __nv_bfloat16  d_Vh[BB * NNP * DD];        // V hi, [b][n][d]
__device__ __nv_bfloat16  d_VhT[BB * DD * NNP];       // V hi transposed, [b][d][n]
__device__ __nv_bfloat16  d_Eh[BB * TT * DD];
__device__ __nv_bfloat16  d_W4h[(size_t)PP * TT * NNP];  // delta = exp(4ns)-1, bf16
__device__ float d_Gs[GSPLIT][PP * TT * DD];          // split partial delta-GEMM
__device__ float d_colsum[BB * DD];                   // exact fp32 col sums of V
__device__ float d_normsq[BB * NN];
__device__ float d_u[BB * MM * DD];
__device__ float d_Zt[PP * TT];
__device__ float d_sExp[PP * TT * MM];
__device__ float d_S[PP];
__device__ float d_betas[BB * TT * MM];

// ---------------- warp MMA + cp.async helpers ----------------
__device__ __forceinline__ uint32_t smem_u32(const void* p) {
    uint32_t a;
    asm("{ .reg .u64 t; cvta.to.shared.u64 t, %1; cvt.u32.u64 %0, t; }"
        : "=r"(a) : "l"(p));
    return a;
}
__device__ __forceinline__ void ldmx4(unsigned* r, uint32_t addr) {
    asm volatile("ldmatrix.sync.aligned.m8n8.x4.shared.b16 {%0,%1,%2,%3}, [%4];"
        : "=r"(r[0]), "=r"(r[1]), "=r"(r[2]), "=r"(r[3]) : "r"(addr));
}
__device__ __forceinline__ void mma_bf16(float* c, const unsigned* a, const unsigned* b) {
    asm volatile("mma.sync.aligned.m16n8k16.row.col.f32.bf16.bf16.f32 "
        "{%0,%1,%2,%3}, {%4,%5,%6,%7}, {%8,%9}, {%0,%1,%2,%3};"
        : "+f"(c[0]), "+f"(c[1]), "+f"(c[2]), "+f"(c[3])
        : "r"(a[0]), "r"(a[1]), "r"(a[2]), "r"(a[3]), "r"(b[0]), "r"(b[1]));
}
__device__ __forceinline__ void cpa16(uint32_t dst, const void* src) {
    asm volatile("cp.async.ca.shared.global [%0], [%1], 16;"
        :: "r"(dst), "l"(src) : "memory");
}
#define CP_COMMIT() asm volatile("cp.async.commit_group;" ::: "memory")
#define CP_WAIT1()  asm volatile("cp.async.wait_group 1;" ::: "memory")

// stage layout (bf16 elems): A[64*40], B[256*40]
#define OFF_B      (64 * 40)
#define STAGE_EL   (64 * 40 + 256 * 40)      // 12800 elems = 25600 B
#define MMA_SMEM   66048                     // max(2 stages=51200, Cs[64][258]=66048)

// ---------------- kernel 0: zero accumulators + pad regions ----------------
__global__ void k_init() {
    const int PAD = NNP - NN;   // 112
    int idx0 = blockIdx.x * blockDim.x + threadIdx.x;
    int stride = gridDim.x * blockDim.x;
    const __nv_bfloat16 z = __float2bfloat16(0.f);
    for (int idx = idx0; idx < BB * NN; idx += stride) d_normsq[idx] = 0.f;
    for (int idx = idx0; idx < PP * TT; idx += stride) d_Zt[idx] = 0.f;
    for (int idx = idx0; idx < PP * TT * MM; idx += stride) d_sExp[idx] = 0.f;
    for (int idx = idx0; idx < BB * DD; idx += stride) d_colsum[idx] = 0.f;
    for (int idx = idx0; idx < BB * PAD * DD; idx += stride) {
        int b = idx / (PAD * DD), r = idx % (PAD * DD);
        int n = NN + r / DD, d = r % DD;
        d_Vh[((size_t)b * NNP + n) * DD + d] = z;
        int d2 = r / PAD, n2 = NN + r % PAD;
        d_VhT[((size_t)b * DD + d2) * NNP + n2] = z;
    }
}

// ---------------- kernel: text -> bf16 ----------------
__global__ void k_prep(const float* __restrict__ text) {
    int idx = blockIdx.x * 256 + threadIdx.x;
    if (idx < BB * TT * DD)
        d_Eh[idx] = __float2bfloat16(text[idx]);
}

// ---------------- kernel 1: transpose image -> Vh/VhT + norms + colsum ----------------
__global__ void __launch_bounds__(256) k_transpose(const float* __restrict__ image) {
    __shared__ float tile[32 * 197];
    const int b = blockIdx.z, m = blockIdx.y, d0 = blockIdx.x * 32;
    const float* src = image + ((size_t)(b * MM + m) * DD + d0) * HWW;
    for (int idx = threadIdx.x; idx < 32 * HWW; idx += 256) {
        int dd = idx / HWW, hw = idx % HWW;
        tile[dd * 197 + hw] = src[idx];
    }
    __syncthreads();
    for (int idx = threadIdx.x; idx < HWW * 32; idx += 256) {
        int nl = idx >> 5, dd = idx & 31;
        int w = nl / 14, h = nl % 14;
        float v = tile[dd * 197 + h * 14 + w];
        d_Vh[((size_t)b * NNP + m * HWW + nl) * DD + d0 + dd] = __float2bfloat16(v);
    }
    for (int idx = threadIdx.x; idx < 32 * HWW; idx += 256) {
        int dd = idx / HWW, nl = idx % HWW;
        int w = nl / 14, h = nl % 14;
        float v = tile[dd * 197 + h * 14 + w];
        d_VhT[((size_t)b * DD + d0 + dd) * NNP + m * HWW + nl] = __float2bfloat16(v);
    }
    if (threadIdx.x < HWW) {
        int nl = threadIdx.x;
        int w = nl / 14, h = nl % 14;
        float s = 0.f;
        #pragma unroll
        for (int dd = 0; dd < 32; dd++) {
            float v = tile[dd * 197 + h * 14 + w];
            s = fmaf(v, v, s);
        }
        atomicAdd(&d_normsq[b * NN + m * HWW + nl], s);
    }
    if (threadIdx.x < 32) {
        int dd = threadIdx.x;
        float s = 0.f;
        for (int hw = 0; hw < HWW; hw++) s += tile[dd * 197 + hw];
        atomicAdd(&d_colsum[b * DD + d0 + dd], s);
    }
}

// ---------------- kernel 2: u[b,m,d] = sum_hw Vh / ||V_row|| ----------------
__global__ void __launch_bounds__(256) k_u() {
    const int m = blockIdx.x, b = blockIdx.y;
    __shared__ float inv[HWW];
    if (threadIdx.x < HWW)
        inv[threadIdx.x] = rsqrtf(d_normsq[b * NN + m * HWW + threadIdx.x]);
    __syncthreads();
    const __nv_bfloat16* vh = d_Vh + ((size_t)b * NNP + m * HWW) * DD;
    for (int d = threadIdx.x; d < DD; d += 256) {
        float acc = 0.f;
        for (int hw = 0; hw < HWW; hw++)
            acc = fmaf(__bfloat162float(vh[(size_t)hw * DD + d]), inv[hw], acc);
        d_u[(size_t)(b * MM + m) * DD + d] = acc;
    }
}

// ---------------- fat-warp MMA mainloop (64 x 256 tile, 4 warps of 64x64) ----------------
struct Frag { float C[4][8][4]; };

__device__ __forceinline__ void mma_chunk1(__nv_bfloat16* stage, int wn,
                                           int arow, int akoff, int brow, int bkoff,
                                           Frag& f) {
    __nv_bfloat16* sA = stage;
    __nv_bfloat16* sB = stage + OFF_B;
    #pragma unroll
    for (int ks = 0; ks < 32; ks += 16) {
        unsigned ah[4][4], bf[8][2];
        #pragma unroll
        for (int mi = 0; mi < 4; mi++)
            ldmx4(ah[mi], smem_u32(sA + (mi * 16 + arow) * 40 + ks + akoff));
        #pragma unroll
        for (int bi = 0; bi < 4; bi++) {
            unsigned r[4];
            ldmx4(r, smem_u32(sB + (wn + bi * 16 + brow) * 40 + ks + bkoff));
            bf[2 * bi][0] = r[0]; bf[2 * bi][1] = r[1];
            bf[2 * bi + 1][0] = r[2]; bf[2 * bi + 1][1] = r[3];
        }
        #pragma unroll
        for (int mi = 0; mi < 4; mi++)
            #pragma unroll
            for (int nj = 0; nj < 8; nj++) mma_bf16(f.C[mi][nj], ah[mi], bf[nj]);
    }
}

// ---------------- kernel 3: sim via 1-term HMMA (128 thr) + softmax ----------------
__global__ void __launch_bounds__(128, 2) k_sim_mma() {
    extern __shared__ __align__(16) char smem[];
    __shared__ int colm[256];
    __shared__ float psum[64][2][4];
    float* Cs = (float*)smem;                       // epilogue [64][258]

    const int tid = threadIdx.x, lane = tid & 31, wid = tid >> 5;
    const int p = blockIdx.y, i = p >> 3, j = p & 7;
    const int n0 = blockIdx.x * 256;
    const int wn = wid * 64;

    Frag f;
    #pragma unroll
    for (int mi = 0; mi < 4; mi++)
        #pragma unroll
        for (int nj = 0; nj < 8; nj++)
            #pragma unroll
            for (int k = 0; k < 4; k++) f.C[mi][nj][k] = 0.f;

    const int lg = lane >> 3;
    const int arow = (lane & 7) + (lg & 1) * 8, akoff = (lg >> 1) * 8;
    const int brow = (lane & 7) + (lg >> 1) * 8, bkoff = (lg & 1) * 8;

    auto load_chunk = [&](int st, int k0) {
        __nv_bfloat16* stage = (__nv_bfloat16*)smem + st * STAGE_EL;
        #pragma unroll
        for (int r = 0; r < 2; r++) {
            int idx = tid + r * 128;
            int row = idx >> 2, q = idx & 3;
            size_t ao = ((size_t)j * TT + row) * DD + k0 + q * 8;
            cpa16(smem_u32(stage + row * 40 + q * 8), d_Eh + ao);
        }
        #pragma unroll
        for (int r = 0; r < 8; r++) {
            int idx = tid + r * 128;
            int row = idx >> 2, q = idx & 3;
            size_t vo = ((size_t)i * NNP + n0 + row) * DD + k0 + q * 8;
            cpa16(smem_u32(stage + OFF_B + row * 40 + q * 8), d_Vh + vo);
        }
    };

    load_chunk(0, 0);
    CP_COMMIT();
    const int NCH = DD / 32;   // 16
    for (int ch = 0; ch < NCH; ch++) {
        if (ch + 1 < NCH) load_chunk((ch + 1) & 1, (ch + 1) * 32);
        CP_COMMIT();
        CP_WAIT1();
        __syncthreads();
        mma_chunk1((__nv_bfloat16*)smem + (ch & 1) * STAGE_EL,
                   wn, arow, akoff, brow, bkoff, f);
        __syncthreads();
    }

    // ---------------- epilogue ----------------
    #pragma unroll
    for (int mi = 0; mi < 4; mi++)
        #pragma unroll
        for (int nj = 0; nj < 8; nj++) {
            int row = mi * 16 + (lane >> 2);
            int col = wn + nj * 8 + (lane & 3) * 2;
            *(float2*)&Cs[row * 258 + col] = make_float2(f.C[mi][nj][0], f.C[mi][nj][1]);
            *(float2*)&Cs[(row + 8) * 258 + col] = make_float2(f.C[mi][nj][2], f.C[mi][nj][3]);
        }
    for (int c = tid; c < 256; c += 128)
        colm[c] = (n0 + c < NN) ? (n0 + c) / HWW : -1;
    __syncthreads();

    // column softmax over t (2 columns per thread), write delta = exp(4 ns) - 1
    for (int col = tid; col < 256; col += 128) {
        float mx = -1e30f;
        for (int t = 0; t < TT; t++) mx = fmaxf(mx, Cs[t * 258 + col]);
        float s = 0.f;
        for (int t = 0; t < TT; t++) {
            float e = __expf(Cs[t * 258 + col] - mx);
            s += e;
            Cs[t * 258 + col] = e;
        }
        float inv = 1.f / s;
        __nv_bfloat16* wh = d_W4h + (size_t)p * TT * NNP + n0 + col;
        for (int t = 0; t < TT; t++) {
            float ns = Cs[t * 258 + col] * inv;
            float en = __expf(ns);
            Cs[t * 258 + col] = en;
            float e4 = en * en; e4 *= e4;
            wh[(size_t)t * NNP] = __float2bfloat16(e4 - 1.0f);
        }
    }
    __syncthreads();
    {   // row reductions: thread (t, half) sums 128 columns
        const int t = tid >> 1, half = tid & 1;
        const int m_base = n0 / HWW;
        float z = 0.f, s0 = 0.f, s1 = 0.f, s2 = 0.f;
        for (int c = half * 128; c < half * 128 + 128; c++) {
            int bm = colm[c];
            if (bm >= 0) {
                float en = Cs[t * 258 + c];
                float e4 = en * en; e4 *= e4;
                z += e4;
                int sel = bm - m_base;
                if (sel == 0) s0 += en; else if (sel == 1) s1 += en; else s2 += en;
            }
        }
        psum[t][half][0] = z; psum[t][half][1] = s0;
        psum[t][half][2] = s1; psum[t][half][3] = s2;
    }
    __syncthreads();
    if (tid < TT) {
        float z  = psum[tid][0][0] + psum[tid][1][0];
        float s0 = psum[tid][0][1] + psum[tid][1][1];
        float s1 = psum[tid][0][2] + psum[tid][1][2];
        float s2 = psum[tid][0][3] + psum[tid][1][3];
        const int m_base = n0 / HWW;
        atomicAdd(&d_Zt[p * TT + tid], z);
        atomicAdd(&d_sExp[((size_t)p * TT + tid) * MM + m_base], s0);
        if (m_base + 1 < MM && s1 != 0.f)
            atomicAdd(&d_sExp[((size_t)p * TT + tid) * MM + m_base + 1], s1);
        if (m_base + 2 < MM && s2 != 0.f)
            atomicAdd(&d_sExp[((size_t)p * TT + tid) * MM + m_base + 2], s2);
    }
}

// ---------------- kernel 4: Gs[s][p,t,d] = delta-GEMM (128 thr) ----------------
__global__ void __launch_bounds__(128, 2) k_gmm_mma() {
    extern __shared__ __align__(16) char smem[];
    const int tid = threadIdx.x, lane = tid & 31, wid = tid >> 5;
    const int p = blockIdx.z, i = p >> 3;
    const int d0 = blockIdx.x * 256;
    const int s = blockIdx.y;
    const int kbase = s * KRANGE;
    const int wn = wid * 64;

    Frag f;
    #pragma unroll
    for (int mi = 0; mi < 4; mi++)
        #pragma unroll
        for (int nj = 0; nj < 8; nj++)
            #pragma unroll
            for (int k = 0; k < 4; k++) f.C[mi][nj][k] = 0.f;

    const int lg = lane >> 3;
    const int arow = (lane & 7) + (lg & 1) * 8, akoff = (lg >> 1) * 8;
    const int brow = (lane & 7) + (lg >> 1) * 8, bkoff = (lg & 1) * 8;

    auto load_chunk = [&](int st, int kb) {
        __nv_bfloat16* stage = (__nv_bfloat16*)smem + st * STAGE_EL;
        #pragma unroll
        for (int r = 0; r < 2; r++) {
            int idx = tid + r * 128;
            int row = idx >> 2, q = idx & 3;
            size_t ao = ((size_t)p * TT + row) * NNP + kb + q * 8;
            cpa16(smem_u32(stage + row * 40 + q * 8), d_W4h + ao);
        }
        #pragma unroll
        for (int r = 0; r < 8; r++) {
            int idx = tid + r * 128;
            int row = idx >> 2, q = idx & 3;
            size_t bo = ((size_t)i * DD + d0 + row) * NNP + kb + q * 8;
            cpa16(smem_u32(stage + OFF_B + row * 40 + q * 8), d_VhT + bo);
        }
    };

    load_chunk(0, kbase);
    CP_COMMIT();
    const int NCH = KRANGE / 32;   // 112
    for (int ch = 0; ch < NCH; ch++) {
        if (ch + 1 < NCH) load_chunk((ch + 1) & 1, kbase + (ch + 1) * 32);
        CP_COMMIT();
        CP_WAIT1();
        __syncthreads();
        mma_chunk1((__nv_bfloat16*)smem + (ch & 1) * STAGE_EL,
                   wn, arow, akoff, brow, bkoff, f);
        __syncthreads();
    }

    float* Gp = &d_Gs[s][((size_t)p * TT) * DD + d0];
    #pragma unroll
    for (int mi = 0; mi < 4; mi++)
        #pragma unroll
        for (int nj = 0; nj < 8; nj++) {
            int row = mi * 16 + (lane >> 2);
            int col = wn + nj * 8 + (lane & 3) * 2;
            *(float2*)&Gp[(size_t)row * DD + col] = make_float2(f.C[mi][nj][0], f.C[mi][nj][1]);
            *(float2*)&Gp[(size_t)(row + 8) * DD + col] = make_float2(f.C[mi][nj][2], f.C[mi][nj][3]);
        }
}

// ---------------- kernel 5: per-pair score S[p] ----------------
__global__ void __launch_bounds__(256) k_score(const float* __restrict__ text) {
    const int p = blockIdx.x, i = p >> 3, j = p & 7;
    __shared__ float sbeta[TT * MM];
    __shared__ float sls[MM];
    __shared__ float sdiag[TT];
    __shared__ float snrm[MM], sdot[MM];
    __shared__ float Es[TT * 128];
    const int tid = threadIdx.x, lane = tid & 31, warp = tid >> 5;
    const float* E = text + (size_t)j * TT * DD;

    for (int idx = tid; idx < TT * MM; idx += 256)
        sbeta[idx] = d_sExp[(size_t)p * TT * MM + idx];
    if (tid < MM) { snrm[tid] = 0.f; sdot[tid] = 0.f; }
    __syncthreads();
    if (tid < MM) {
        float s = 0.f;
        for (int t = 0; t < TT; t++) s += sbeta[t * MM + tid];
        sls[tid] = 1.0f / s;
    }
    __syncthreads();
    for (int idx = tid; idx < TT * MM; idx += 256) {
        float v = sbeta[idx] * sls[idx % MM];
        sbeta[idx] = v;
        if (i == j) d_betas[(size_t)i * TT * MM + idx] = v;
    }
    __syncthreads();

    for (int t = warp; t < TT; t += 8) {
        const size_t off = ((size_t)p * TT + t) * DD;
        const float* Er = E + (size_t)t * DD;
        const float* Ci = d_colsum + i * DD;
        float s = 0.f;
        for (int d = lane; d < DD; d += 32) {
            float g = d_Gs[0][off + d] + d_Gs[1][off + d] + Ci[d];
            s = fmaf(g, Er[d], s);
        }
        #pragma unroll
        for (int o = 16; o; o >>= 1) s += __shfl_down_sync(0xffffffffu, s, o);
        if (lane == 0) sdiag[t] = s / d_Zt[p * TT + t];
    }

    const float* U = d_u + (size_t)i * MM * DD;
    const int grp = tid >> 7;
    const int dl = tid & 127;
    for (int d0 = 0; d0 < DD; d0 += 128) {
        __syncthreads();
        for (int idx = tid; idx < TT * 128; idx += 256) {
            int t = idx >> 7, dloc = idx & 127;
            Es[idx] = E[(size_t)t * DD + d0 + dloc];
        }
        __syncthreads();
        for (int m = grp; m < MM; m += 2) {
            float v = 0.f;
            #pragma unroll 16
            for (int t = 0; t < TT; t++)
                v = fmaf(sbeta[t * MM + m], Es[t * 128 + dl], v);
            float nr = v * v;
            float dt = v * U[(size_t)m * DD + d0 + dl];
            #pragma unroll
            for (int o = 16; o; o >>= 1) {
                nr += __shfl_down_sync(0xffffffffu, nr, o);
                dt += __shfl_down_sync(0xffffffffu, dt, o);
            }
            if (lane == 0) { atomicAdd(&snrm[m], nr); atomicAdd(&sdot[m], dt); }
        }
    }
    __syncthreads();
    if (tid == 0) {
        float se = 0.f;
        for (int t = 0; t < TT; t++) se += expf(G2 * sdiag[t]);
        float r_qd = (1.0f / G2) * logf(se);
        float sm = 0.f;
        for (int m = 0; m < MM; m++)
            sm += expf(sdot[m] / ((float)HWW * sqrtf(snrm[m])));
        d_S[p] = r_qd + (1.0f / G2) * logf(sm);
    }
}

// ---------------- kernel 6: final scalar ----------------
__global__ void __launch_bounds__(256) k_final(const int* __restrict__ spinds,
                                               float* __restrict__ out) {
    __shared__ float sbm[TT * MM];
    __shared__ float red[8];
    __shared__ float regsum;
    const int tid = threadIdx.x, lane = tid & 31, warp = tid >> 5;
    if (tid == 0) regsum = 0.f;
    for (int b = 0; b < BB; b++) {
        __syncthreads();
        for (int idx = tid; idx < TT * MM; idx += 256)
            sbm[idx] = d_betas[(size_t)b * TT * MM + idx];
        __syncthreads();
        float lsum = 0.f;
        for (int idx = tid; idx < MM * MM; idx += 256) {
            int a = idx / MM, c = idx % MM;
            float v = 0.f;
            for (int t = 0; t < TT; t++)
                v = fmaf(sbm[t * MM + a], sbm[t * MM + c], v);
            lsum = fmaf(v, v, lsum);
        }
        for (int t = tid; t < TT; t += 256) {
            float v = 0.f;
            for (int m = 0; m < MM; m++)
                v = fmaf(sbm[t * MM + m], sbm[t * MM + m], v);
            lsum -= v * v;
        }
        #pragma unroll
        for (int o = 16; o; o >>= 1)
            lsum += __shfl_down_sync(0xffffffffu, lsum, o);
        if (lane == 0) red[warp] = lsum;
        __syncthreads();
        if (tid == 0) {
            float s = 0.f;
            for (int w = 0; w < 8; w++) s += red[w];
            regsum += sqrtf(fmaxf(s, 0.f));
        }
    }
    __syncthreads();
    if (tid == 0) {
        float l1 = 0.f, l2 = 0.f;
        for (int a = 0; a < BB; a++) {
            float num = expf(d_S[a * BB + a]);
            float pdq = 0.f, pqd = 0.f;
            for (int k = 0; k < 5; k++) {
                int sp = spinds[a * 5 + k];
                pdq += expf(d_S[a * BB + sp]);
                pqd += expf(d_S[sp * BB + a]);
            }
            l1 += num / pdq;
            l2 += num / pqd;
        }
        out[0] = -(l1 / BB) - (l2 / BB) + regsum / (float)(BB * TT * MM);
    }
}

// ---------------- launcher ----------------
extern "C" void kernel_launch(void* const* d_in, const int* in_sizes, int n_in,
                              void* d_out, int out_size) {
    const float* image  = (const float*)d_in[0];
    const float* text   = (const float*)d_in[1];
    const int*   spinds = (const int*)d_in[3];
    float* out = (float*)d_out;

    cudaFuncSetAttribute(k_sim_mma, cudaFuncAttributeMaxDynamicSharedMemorySize, MMA_SMEM);
    cudaFuncSetAttribute(k_gmm_mma, cudaFuncAttributeMaxDynamicSharedMemorySize, MMA_SMEM);

    k_init<<<1024, 256>>>();
    k_prep<<<(BB * TT * DD) / 256, 256>>>(text);
    {
        dim3 g(16, MM, BB);
        k_transpose<<<g, 256>>>(image);
    }
    {
        dim3 g(NNP / 256, PP);          // 28 x 64  (4th launch -> profiled)
        k_sim_mma<<<g, 128, MMA_SMEM>>>();
    }
    {
        dim3 g(MM, BB);
        k_u<<<g, 256>>>();
    }
    {
        dim3 g(DD / 256, GSPLIT, PP);   // 2 x 2 x 64
        k_gmm_mma<<<g, 128, MMA_SMEM>>>();
    }
    k_score<<<PP, 256>>>(text);
    k_final<<<1, 256>>>(spinds, out);
}

// round 11
// speedup vs baseline: 3.3418x; 1.7542x over previous
#include <cuda_runtime.h>
#include <cuda_bf16.h>
#include <math.h>
#include <stdint.h>

#define BB  8
#define MM  36
#define DD  512
#define HWW 196
#define TT  64
#define NN  7056
#define NNP 7168          // padded N (multiple of 256)
#define PP  64
#define G2  5.0f

// ---------------- scratch (device globals; no allocation) ----------------
__device__ __nv_bfloat16  d_Vh[BB * NNP * DD];        // V bf16, [b][n][d]
__device__ __nv_bfloat16  d_Eh[BB * TT * DD];
__device__ float d_normsq[BB * NN];
__device__ float d_u[BB * MM * DD];
__device__ float d_Zt[PP * TT];
__device__ float d_dacc[PP * TT];                     // sum_n e4 * sim_raw
__device__ float d_sExp[PP * TT * MM];
__device__ float d_snrm[PP * MM];
__device__ float d_sdot[PP * MM];
__device__ float d_betas[BB * TT * MM];

// ---------------- warp MMA + cp.async helpers ----------------
__device__ __forceinline__ uint32_t smem_u32(const void* p) {
    uint32_t a;
    asm("{ .reg .u64 t; cvta.to.shared.u64 t, %1; cvt.u32.u64 %0, t; }"
        : "=r"(a) : "l"(p));
    return a;
}
__device__ __forceinline__ void ldmx4(unsigned* r, uint32_t addr) {
    asm volatile("ldmatrix.sync.aligned.m8n8.x4.shared.b16 {%0,%1,%2,%3}, [%4];"
        : "=r"(r[0]), "=r"(r[1]), "=r"(r[2]), "=r"(r[3]) : "r"(addr));
}
__device__ __forceinline__ void mma_bf16(float* c, const unsigned* a, const unsigned* b) {
    asm volatile("mma.sync.aligned.m16n8k16.row.col.f32.bf16.bf16.f32 "
        "{%0,%1,%2,%3}, {%4,%5,%6,%7}, {%8,%9}, {%0,%1,%2,%3};"
        : "+f"(c[0]), "+f"(c[1]), "+f"(c[2]), "+f"(c[3])
        : "r"(a[0]), "r"(a[1]), "r"(a[2]), "r"(a[3]), "r"(b[0]), "r"(b[1]));
}
__device__ __forceinline__ void cpa16(uint32_t dst, const void* src) {
    asm volatile("cp.async.ca.shared.global [%0], [%1], 16;"
        :: "r"(dst), "l"(src) : "memory");
}
#define CP_COMMIT() asm volatile("cp.async.commit_group;" ::: "memory")
#define CP_WAIT1()  asm volatile("cp.async.wait_group 1;" ::: "memory")

// stage layout (bf16 elems): A[64*40], B[256*40]
#define OFF_B      (64 * 40)
#define STAGE_EL   (64 * 40 + 256 * 40)      // 12800 elems = 25600 B
// dynamic smem = max(2 stages = 51200, epilogue Xs[64][130]+En[64][130] = 66560)
#define MMA_SMEM   66560

// ---------------- kernel 0: zero accumulators + pad regions ----------------
__global__ void k_init() {
    const int PAD = NNP - NN;   // 112
    int idx0 = blockIdx.x * blockDim.x + threadIdx.x;
    int stride = gridDim.x * blockDim.x;
    const __nv_bfloat16 z = __float2bfloat16(0.f);
    for (int idx = idx0; idx < BB * NN; idx += stride) d_normsq[idx] = 0.f;
    for (int idx = idx0; idx < PP * TT; idx += stride) { d_Zt[idx] = 0.f; d_dacc[idx] = 0.f; }
    for (int idx = idx0; idx < PP * TT * MM; idx += stride) d_sExp[idx] = 0.f;
    for (int idx = idx0; idx < PP * MM; idx += stride) { d_snrm[idx] = 0.f; d_sdot[idx] = 0.f; }
    for (int idx = idx0; idx < BB * PAD * DD; idx += stride) {
        int b = idx / (PAD * DD), r = idx % (PAD * DD);
        int n = NN + r / DD, d = r % DD;
        d_Vh[((size_t)b * NNP + n) * DD + d] = z;
    }
}

// ---------------- kernel: text -> bf16 ----------------
__global__ void k_prep(const float* __restrict__ text) {
    int idx = blockIdx.x * 256 + threadIdx.x;
    if (idx < BB * TT * DD)
        d_Eh[idx] = __float2bfloat16(text[idx]);
}

// ---------------- kernel 1: transpose image -> Vh + norms ----------------
__global__ void __launch_bounds__(256) k_transpose(const float* __restrict__ image) {
    __shared__ float tile[32 * 197];
    const int b = blockIdx.z, m = blockIdx.y, d0 = blockIdx.x * 32;
    const float* src = image + ((size_t)(b * MM + m) * DD + d0) * HWW;
    for (int idx = threadIdx.x; idx < 32 * HWW; idx += 256) {
        int dd = idx / HWW, hw = idx % HWW;
        tile[dd * 197 + hw] = src[idx];
    }
    __syncthreads();
    for (int idx = threadIdx.x; idx < HWW * 32; idx += 256) {
        int nl = idx >> 5, dd = idx & 31;
        int w = nl / 14, h = nl % 14;
        float v = tile[dd * 197 + h * 14 + w];
        d_Vh[((size_t)b * NNP + m * HWW + nl) * DD + d0 + dd] = __float2bfloat16(v);
    }
    if (threadIdx.x < HWW) {
        int nl = threadIdx.x;
        int w = nl / 14, h = nl % 14;
        float s = 0.f;
        #pragma unroll
        for (int dd = 0; dd < 32; dd++) {
            float v = tile[dd * 197 + h * 14 + w];
            s = fmaf(v, v, s);
        }
        atomicAdd(&d_normsq[b * NN + m * HWW + nl], s);
    }
}

// ---------------- kernel 2: u[b,m,d] = sum_hw Vh / ||V_row|| ----------------
__global__ void __launch_bounds__(256) k_u() {
    const int m = blockIdx.x, b = blockIdx.y;
    __shared__ float inv[HWW];
    if (threadIdx.x < HWW)
        inv[threadIdx.x] = rsqrtf(d_normsq[b * NN + m * HWW + threadIdx.x]);
    __syncthreads();
    const __nv_bfloat16* vh = d_Vh + ((size_t)b * NNP + m * HWW) * DD;
    for (int d = threadIdx.x; d < DD; d += 256) {
        float acc = 0.f;
        for (int hw = 0; hw < HWW; hw++)
            acc = fmaf(__bfloat162float(vh[(size_t)hw * DD + d]), inv[hw], acc);
        d_u[(size_t)(b * MM + m) * DD + d] = acc;
    }
}

// ---------------- fat-warp MMA mainloop (64 x 256 tile, 4 warps of 64x64) ----------------
struct Frag { float C[4][8][4]; };

__device__ __forceinline__ void mma_chunk1(__nv_bfloat16* stage, int wn,
                                           int arow, int akoff, int brow, int bkoff,
                                           Frag& f) {
    __nv_bfloat16* sA = stage;
    __nv_bfloat16* sB = stage + OFF_B;
    #pragma unroll
    for (int ks = 0; ks < 32; ks += 16) {
        unsigned ah[4][4], bf[8][2];
        #pragma unroll
        for (int mi = 0; mi < 4; mi++)
            ldmx4(ah[mi], smem_u32(sA + (mi * 16 + arow) * 40 + ks + akoff));
        #pragma unroll
        for (int bi = 0; bi < 4; bi++) {
            unsigned r[4];
            ldmx4(r, smem_u32(sB + (wn + bi * 16 + brow) * 40 + ks + bkoff));
            bf[2 * bi][0] = r[0]; bf[2 * bi][1] = r[1];
            bf[2 * bi + 1][0] = r[2]; bf[2 * bi + 1][1] = r[3];
        }
        #pragma unroll
        for (int mi = 0; mi < 4; mi++)
            #pragma unroll
            for (int nj = 0; nj < 8; nj++) mma_bf16(f.C[mi][nj], ah[mi], bf[nj]);
    }
}

// ---------------- kernel 3: sim HMMA + softmax + in-kernel diag/Zt/sExp ----------------
__global__ void __launch_bounds__(128, 2) k_sim_mma() {
    extern __shared__ __align__(16) char smem[];
    __shared__ int colm[128];
    __shared__ float psum[64][2][5];
    float* Xs = (float*)smem;                       // raw sim [64][130]
    float* En = Xs + 64 * 130;                      // exp(norm_sim) [64][130]

    const int tid = threadIdx.x, lane = tid & 31, wid = tid >> 5;
    const int p = blockIdx.y, i = p >> 3, j = p & 7;
    const int n0 = blockIdx.x * 256;
    const int wn = wid * 64;
    const int m_base = n0 / HWW;

    Frag f;
    #pragma unroll
    for (int mi = 0; mi < 4; mi++)
        #pragma unroll
        for (int nj = 0; nj < 8; nj++)
            #pragma unroll
            for (int k = 0; k < 4; k++) f.C[mi][nj][k] = 0.f;

    const int lg = lane >> 3;
    const int arow = (lane & 7) + (lg & 1) * 8, akoff = (lg >> 1) * 8;
    const int brow = (lane & 7) + (lg >> 1) * 8, bkoff = (lg & 1) * 8;

    auto load_chunk = [&](int st, int k0) {
        __nv_bfloat16* stage = (__nv_bfloat16*)smem + st * STAGE_EL;
        #pragma unroll
        for (int r = 0; r < 2; r++) {
            int idx = tid + r * 128;
            int row = idx >> 2, q = idx & 3;
            size_t ao = ((size_t)j * TT + row) * DD + k0 + q * 8;
            cpa16(smem_u32(stage + row * 40 + q * 8), d_Eh + ao);
        }
        #pragma unroll
        for (int r = 0; r < 8; r++) {
            int idx = tid + r * 128;
            int row = idx >> 2, q = idx & 3;
            size_t vo = ((size_t)i * NNP + n0 + row) * DD + k0 + q * 8;
            cpa16(smem_u32(stage + OFF_B + row * 40 + q * 8), d_Vh + vo);
        }
    };

    load_chunk(0, 0);
    CP_COMMIT();
    const int NCH = DD / 32;   // 16
    for (int ch = 0; ch < NCH; ch++) {
        if (ch + 1 < NCH) load_chunk((ch + 1) & 1, (ch + 1) * 32);
        CP_COMMIT();
        CP_WAIT1();
        __syncthreads();
        mma_chunk1((__nv_bfloat16*)smem + (ch & 1) * STAGE_EL,
                   wn, arow, akoff, brow, bkoff, f);
        __syncthreads();
    }

    // ---------------- epilogue: two halves of 128 columns ----------------
    for (int h = 0; h < 2; h++) {
        __syncthreads();
        if ((wid >> 1) == h) {
            const int wl = wid & 1;                 // 0/1 within half
            #pragma unroll
            for (int mi = 0; mi < 4; mi++)
                #pragma unroll
                for (int nj = 0; nj < 8; nj++) {
                    int row = mi * 16 + (lane >> 2);
                    int col = wl * 64 + nj * 8 + (lane & 3) * 2;
                    *(float2*)&Xs[row * 130 + col] = make_float2(f.C[mi][nj][0], f.C[mi][nj][1]);
                    *(float2*)&Xs[(row + 8) * 130 + col] = make_float2(f.C[mi][nj][2], f.C[mi][nj][3]);
                }
        }
        {
            int gc = n0 + h * 128 + tid;
            colm[tid] = (gc < NN) ? gc / HWW : -1;
        }
        __syncthreads();
        // column phase: softmax over t (128 threads, 1 col each); store en
        {
            const int col = tid;
            float mx = -1e30f;
            for (int t = 0; t < TT; t++) mx = fmaxf(mx, Xs[t * 130 + col]);
            float s = 0.f;
            for (int t = 0; t < TT; t++) s += __expf(Xs[t * 130 + col] - mx);
            float inv = 1.f / s;
            for (int t = 0; t < TT; t++) {
                float pexp = __expf(Xs[t * 130 + col] - mx);
                float ns = pexp * inv;
                En[t * 130 + col] = __expf(ns);
            }
        }
        __syncthreads();
        // row phase: per (t, half-of-128), reduce 64 cols: Zt, dacc, sExp
        {
            const int t = tid >> 1, q = tid & 1;
            float z = 0.f, dv = 0.f, s0 = 0.f, s1 = 0.f, s2 = 0.f;
            for (int c = q * 64; c < q * 64 + 64; c++) {
                int bm = colm[c];
                if (bm >= 0) {
                    float en = En[t * 130 + c];
                    float e4 = en * en; e4 *= e4;
                    z += e4;
                    dv = fmaf(e4, Xs[t * 130 + c], dv);
                    int sel = bm - m_base;
                    if (sel == 0) s0 += en; else if (sel == 1) s1 += en; else s2 += en;
                }
            }
            psum[t][q][0] = z;  psum[t][q][1] = dv;
            psum[t][q][2] = s0; psum[t][q][3] = s1; psum[t][q][4] = s2;
        }
        __syncthreads();
        if (tid < TT) {
            float z  = psum[tid][0][0] + psum[tid][1][0];
            float dv = psum[tid][0][1] + psum[tid][1][1];
            float s0 = psum[tid][0][2] + psum[tid][1][2];
            float s1 = psum[tid][0][3] + psum[tid][1][3];
            float s2 = psum[tid][0][4] + psum[tid][1][4];
            atomicAdd(&d_Zt[p * TT + tid], z);
            atomicAdd(&d_dacc[p * TT + tid], dv);
            if (s0 != 0.f)
                atomicAdd(&d_sExp[((size_t)p * TT + tid) * MM + m_base], s0);
            if (m_base + 1 < MM && s1 != 0.f)
                atomicAdd(&d_sExp[((size_t)p * TT + tid) * MM + m_base + 1], s1);
            if (m_base + 2 < MM && s2 != 0.f)
                atomicAdd(&d_sExp[((size_t)p * TT + tid) * MM + m_base + 2], s2);
        }
    }
}

// ---------------- kernel 5: per-pair e_prime partials (grid PP x 4) ----------------
__global__ void __launch_bounds__(256) k_score(const float* __restrict__ text) {
    const int p = blockIdx.x, i = p >> 3, j = p & 7;
    const int d0 = blockIdx.y * 128;
    __shared__ float sbeta[TT * MM];
    __shared__ float sls[MM];
    __shared__ float Es[TT * 128];
    const int tid = threadIdx.x, lane = tid & 31;
    const float* E = text + (size_t)j * TT * DD;

    for (int idx = tid; idx < TT * MM; idx += 256)
        sbeta[idx] = d_sExp[(size_t)p * TT * MM + idx];
    __syncthreads();
    if (tid < MM) {
        float s = 0.f;
        for (int t = 0; t < TT; t++) s += sbeta[t * MM + tid];
        sls[tid] = 1.0f / s;
    }
    __syncthreads();
    for (int idx = tid; idx < TT * MM; idx += 256) {
        float v = sbeta[idx] * sls[idx % MM];
        sbeta[idx] = v;
        if (blockIdx.y == 0 && i == j) d_betas[(size_t)i * TT * MM + idx] = v;
    }
    for (int idx = tid; idx < TT * 128; idx += 256) {
        int t = idx >> 7, dloc = idx & 127;
        Es[idx] = E[(size_t)t * DD + d0 + dloc];
    }
    __syncthreads();

    const float* U = d_u + (size_t)i * MM * DD;
    const int grp = tid >> 7;
    const int dl = tid & 127;
    for (int m = grp; m < MM; m += 2) {
        float v = 0.f;
        #pragma unroll 16
        for (int t = 0; t < TT; t++)
            v = fmaf(sbeta[t * MM + m], Es[t * 128 + dl], v);
        float nr = v * v;
        float dt = v * U[(size_t)m * DD + d0 + dl];
        #pragma unroll
        for (int o = 16; o; o >>= 1) {
            nr += __shfl_down_sync(0xffffffffu, nr, o);
            dt += __shfl_down_sync(0xffffffffu, dt, o);
        }
        if (lane == 0) {
            atomicAdd(&d_snrm[p * MM + m], nr);
            atomicAdd(&d_sdot[p * MM + m], dt);
        }
    }
}

// ---------------- kernel 6: S[p] + final scalar ----------------
__global__ void __launch_bounds__(256) k_final(const int* __restrict__ spinds,
                                               float* __restrict__ out) {
    __shared__ float S[PP];
    __shared__ float sbm[TT * MM];
    __shared__ float red[8];
    __shared__ float regsum;
    const int tid = threadIdx.x, lane = tid & 31, warp = tid >> 5;

    if (tid < PP) {
        const int p = tid;
        float se = 0.f;
        for (int t = 0; t < TT; t++)
            se += expf(G2 * d_dacc[p * TT + t] / d_Zt[p * TT + t]);
        float r_qd = (1.0f / G2) * logf(se);
        float sm = 0.f;
        for (int m = 0; m < MM; m++)
            sm += expf(d_sdot[p * MM + m] / ((float)HWW * sqrtf(d_snrm[p * MM + m])));
        S[p] = r_qd + (1.0f / G2) * logf(sm);
    }
    if (tid == 0) regsum = 0.f;

    for (int b = 0; b < BB; b++) {
        __syncthreads();
        for (int idx = tid; idx < TT * MM; idx += 256)
            sbm[idx] = d_betas[(size_t)b * TT * MM + idx];
        __syncthreads();
        float lsum = 0.f;
        for (int idx = tid; idx < MM * MM; idx += 256) {
            int a = idx / MM, c = idx % MM;
            float v = 0.f;
            for (int t = 0; t < TT; t++)
                v = fmaf(sbm[t * MM + a], sbm[t * MM + c], v);
            lsum = fmaf(v, v, lsum);
        }
        for (int t = tid; t < TT; t += 256) {
            float v = 0.f;
            for (int m = 0; m < MM; m++)
                v = fmaf(sbm[t * MM + m], sbm[t * MM + m], v);
            lsum -= v * v;
        }
        #pragma unroll
        for (int o = 16; o; o >>= 1)
            lsum += __shfl_down_sync(0xffffffffu, lsum, o);
        if (lane == 0) red[warp] = lsum;
        __syncthreads();
        if (tid == 0) {
            float s = 0.f;
            for (int w = 0; w < 8; w++) s += red[w];
            regsum += sqrtf(fmaxf(s, 0.f));
        }
    }
    __syncthreads();
    if (tid == 0) {
        float l1 = 0.f, l2 = 0.f;
        for (int a = 0; a < BB; a++) {
            float num = expf(S[a * BB + a]);
            float pdq = 0.f, pqd = 0.f;
            for (int k = 0; k < 5; k++) {
                int sp = spinds[a * 5 + k];
                pdq += expf(S[a * BB + sp]);
                pqd += expf(S[sp * BB + a]);
            }
            l1 += num / pdq;
            l2 += num / pqd;
        }
        out[0] = -(l1 / BB) - (l2 / BB) + regsum / (float)(BB * TT * MM);
    }
}

// ---------------- launcher ----------------
extern "C" void kernel_launch(void* const* d_in, const int* in_sizes, int n_in,
                              void* d_out, int out_size) {
    const float* image  = (const float*)d_in[0];
    const float* text   = (const float*)d_in[1];
    const int*   spinds = (const int*)d_in[3];
    float* out = (float*)d_out;

    cudaFuncSetAttribute(k_sim_mma, cudaFuncAttributeMaxDynamicSharedMemorySize, MMA_SMEM);

    k_init<<<1024, 256>>>();
    k_prep<<<(BB * TT * DD) / 256, 256>>>(text);
    {
        dim3 g(16, MM, BB);
        k_transpose<<<g, 256>>>(image);
    }
    {
        dim3 g(NNP / 256, PP);          // 28 x 64  (4th launch -> profiled)
        k_sim_mma<<<g, 128, MMA_SMEM>>>();
    }
    {
        dim3 g(MM, BB);
        k_u<<<g, 256>>>();
    }
    {
        dim3 g(PP, 4);                  // 64 x 4 d-chunks
        k_score<<<g, 256>>>(text);
    }
    k_final<<<1, 256>>>(spinds, out);
}